// round 1
// baseline (speedup 1.0000x reference)
#include <cuda_runtime.h>
#include <math.h>

#define BB 16
#define SS 2048
#define DD 1024
#define NN 16
#define M_TOT (BB*SS)   // 32768 tokens

// Scratch (allocation-free rule: __device__ globals)
__device__ float g_a[M_TOT*NN];
__device__ float g_b[M_TOT*NN];
__device__ float g_h[M_TOT*NN];

// ---------------------------------------------------------------------------
// Kernel 1: a = tanh(x@WA^T), b = x@WB^T     (GEMM M=32768, N=32, K=1024)
// ---------------------------------------------------------------------------
__global__ __launch_bounds__(256) void ab_kernel(const float* __restrict__ x,
                                                 const float* __restrict__ WA,
                                                 const float* __restrict__ WB)
{
    __shared__ float Xs[128][33];
    __shared__ float Ws[32][33];
    const int tid = threadIdx.x;
    const int m0  = blockIdx.x * 128;
    const int otx = tid & 7;    // output group: 4 outputs each -> 32
    const int tty = tid >> 3;   // token group: 4 tokens each -> 128

    float acc[4][4] = {};

    for (int k0 = 0; k0 < DD; k0 += 32) {
        // X tile: 128 x 32 floats = 1024 float4
        #pragma unroll
        for (int r = 0; r < 4; r++) {
            int idx = tid + r * 256;
            int t  = idx >> 3;
            int kv = idx & 7;
            float4 v = *(const float4*)(x + (size_t)(m0 + t) * DD + k0 + kv * 4);
            Xs[t][kv*4+0] = v.x; Xs[t][kv*4+1] = v.y;
            Xs[t][kv*4+2] = v.z; Xs[t][kv*4+3] = v.w;
        }
        // W tile: rows 0..15 = WA, 16..31 = WB ; 32 x 32 floats = 256 float4
        {
            int n  = tid >> 3;
            int kv = tid & 7;
            const float* Wsrc = (n < 16) ? (WA + (size_t)n * DD)
                                         : (WB + (size_t)(n - 16) * DD);
            float4 v = *(const float4*)(Wsrc + k0 + kv * 4);
            Ws[n][kv*4+0] = v.x; Ws[n][kv*4+1] = v.y;
            Ws[n][kv*4+2] = v.z; Ws[n][kv*4+3] = v.w;
        }
        __syncthreads();

        #pragma unroll
        for (int kk = 0; kk < 32; kk++) {
            float xr[4], wr[4];
            #pragma unroll
            for (int i = 0; i < 4; i++) xr[i] = Xs[tty*4 + i][kk];
            #pragma unroll
            for (int j = 0; j < 4; j++) wr[j] = Ws[otx*4 + j][kk];
            #pragma unroll
            for (int i = 0; i < 4; i++)
                #pragma unroll
                for (int j = 0; j < 4; j++)
                    acc[i][j] = fmaf(xr[i], wr[j], acc[i][j]);
        }
        __syncthreads();
    }

    #pragma unroll
    for (int i = 0; i < 4; i++) {
        int t = m0 + tty*4 + i;
        #pragma unroll
        for (int j = 0; j < 4; j++) {
            int n = otx*4 + j;
            if (n < 16) g_a[(size_t)t * NN + n]        = tanhf(acc[i][j]);
            else        g_b[(size_t)t * NN + (n - 16)] = acc[i][j];
        }
    }
}

// ---------------------------------------------------------------------------
// Kernel 2: sequential recurrence h_t = a_t*h_{t-1} + b_t
// 256 independent chains (batch, n); single block.
// ---------------------------------------------------------------------------
__global__ __launch_bounds__(256) void scan_kernel()
{
    const int tid   = threadIdx.x;       // 0..255
    const int batch = tid >> 4;
    const int n     = tid & 15;
    float h = 0.0f;
    size_t base = (size_t)batch * SS * NN + n;
    #pragma unroll 4
    for (int t = 0; t < SS; t++) {
        size_t idx = base + (size_t)t * NN;
        h = fmaf(g_a[idx], h, g_b[idx]);
        g_h[idx] = h;
    }
}

// ---------------------------------------------------------------------------
// Kernel 3: fused  C1 = x@Wg^T, C2 = x@WD^T  (shared X tile),
// epilogue: y = (hs@WC^T)*sigmoid(C1+bg) + (C2+bD)*(1-sigmoid(C1+bg))
// Tile: 128 tokens x 64 outputs, 256 threads, thread tile 8x4 per GEMM.
// ---------------------------------------------------------------------------
__global__ __launch_bounds__(256) void main_kernel(const float* __restrict__ x,
                                                   const float* __restrict__ WC,
                                                   const float* __restrict__ WD,
                                                   const float* __restrict__ bD,
                                                   const float* __restrict__ Wg,
                                                   const float* __restrict__ bg,
                                                   float* __restrict__ out)
{
    __shared__ __align__(16) float Xs[128][17];
    __shared__ __align__(16) float Wgs[16][64];   // K-major
    __shared__ __align__(16) float WDs[16][64];   // K-major
    __shared__ __align__(16) float Hs[128][16];
    __shared__ __align__(16) float WCs[64][16];

    const int tid = threadIdx.x;
    const int tx  = tid & 15;    // 4 outputs each -> 64
    const int ty  = tid >> 4;    // 8 tokens  each -> 128
    const int m0  = blockIdx.y * 128;
    const int e0  = blockIdx.x * 64;

    // Preload hs tile [128,16] (512 float4) and WC tile [64,16] (256 float4)
    #pragma unroll
    for (int r = 0; r < 2; r++) {
        int idx = tid + r * 256;
        int t  = idx >> 2;
        int kv = idx & 3;
        float4 v = *(const float4*)(g_h + (size_t)(m0 + t) * NN + kv * 4);
        Hs[t][kv*4+0] = v.x; Hs[t][kv*4+1] = v.y;
        Hs[t][kv*4+2] = v.z; Hs[t][kv*4+3] = v.w;
    }
    {
        int e  = tid >> 2;
        int kv = tid & 3;
        float4 v = *(const float4*)(WC + (size_t)(e0 + e) * NN + kv * 4);
        WCs[e][kv*4+0] = v.x; WCs[e][kv*4+1] = v.y;
        WCs[e][kv*4+2] = v.z; WCs[e][kv*4+3] = v.w;
    }

    float accG[8][4] = {};
    float accD[8][4] = {};

    for (int k0 = 0; k0 < DD; k0 += 16) {
        // X tile: 128 x 16 = 512 float4
        #pragma unroll
        for (int r = 0; r < 2; r++) {
            int idx = tid + r * 256;
            int t  = idx >> 2;
            int kv = idx & 3;
            float4 v = *(const float4*)(x + (size_t)(m0 + t) * DD + k0 + kv * 4);
            Xs[t][kv*4+0] = v.x; Xs[t][kv*4+1] = v.y;
            Xs[t][kv*4+2] = v.z; Xs[t][kv*4+3] = v.w;
        }
        // Wg/WD tiles stored K-major: Ws[k][e] ; 64 e x 4 kvec = 256 float4 each
        {
            int e  = tid >> 2;
            int kv = tid & 3;
            float4 v = *(const float4*)(Wg + (size_t)(e0 + e) * DD + k0 + kv * 4);
            Wgs[kv*4+0][e] = v.x; Wgs[kv*4+1][e] = v.y;
            Wgs[kv*4+2][e] = v.z; Wgs[kv*4+3][e] = v.w;
            float4 w = *(const float4*)(WD + (size_t)(e0 + e) * DD + k0 + kv * 4);
            WDs[kv*4+0][e] = w.x; WDs[kv*4+1][e] = w.y;
            WDs[kv*4+2][e] = w.z; WDs[kv*4+3][e] = w.w;
        }
        __syncthreads();

        #pragma unroll
        for (int kk = 0; kk < 16; kk++) {
            float xr[8];
            #pragma unroll
            for (int i = 0; i < 8; i++) xr[i] = Xs[ty*8 + i][kk];
            float4 wg = *(const float4*)&Wgs[kk][tx*4];
            float4 wd = *(const float4*)&WDs[kk][tx*4];
            #pragma unroll
            for (int i = 0; i < 8; i++) {
                accG[i][0] = fmaf(xr[i], wg.x, accG[i][0]);
                accG[i][1] = fmaf(xr[i], wg.y, accG[i][1]);
                accG[i][2] = fmaf(xr[i], wg.z, accG[i][2]);
                accG[i][3] = fmaf(xr[i], wg.w, accG[i][3]);
                accD[i][0] = fmaf(xr[i], wd.x, accD[i][0]);
                accD[i][1] = fmaf(xr[i], wd.y, accD[i][1]);
                accD[i][2] = fmaf(xr[i], wd.z, accD[i][2]);
                accD[i][3] = fmaf(xr[i], wd.w, accD[i][3]);
            }
        }
        __syncthreads();
    }

    // Epilogue
    float bgv[4], bDv[4];
    #pragma unroll
    for (int j = 0; j < 4; j++) {
        int e = e0 + tx*4 + j;
        bgv[j] = bg[e];
        bDv[j] = bD[e];
    }
    #pragma unroll
    for (int i = 0; i < 8; i++) {
        int t = m0 + ty*8 + i;
        float4 o;
        float res[4];
        #pragma unroll
        for (int j = 0; j < 4; j++) {
            float yv = 0.0f;
            #pragma unroll
            for (int n = 0; n < 16; n++)
                yv = fmaf(Hs[ty*8 + i][n], WCs[tx*4 + j][n], yv);
            float gv  = 1.0f / (1.0f + __expf(-(accG[i][j] + bgv[j])));
            float dxv = accD[i][j] + bDv[j];
            res[j] = yv * gv + dxv * (1.0f - gv);
        }
        o.x = res[0]; o.y = res[1]; o.z = res[2]; o.w = res[3];
        *(float4*)(out + (size_t)t * DD + e0 + tx*4) = o;
    }
}

// ---------------------------------------------------------------------------
extern "C" void kernel_launch(void* const* d_in, const int* in_sizes, int n_in,
                              void* d_out, int out_size)
{
    const float* x  = (const float*)d_in[0];
    const float* WA = (const float*)d_in[1];
    const float* WB = (const float*)d_in[2];
    const float* WC = (const float*)d_in[3];
    const float* WD = (const float*)d_in[4];
    const float* bD = (const float*)d_in[5];
    const float* Wg = (const float*)d_in[6];
    const float* bg = (const float*)d_in[7];
    float* out = (float*)d_out;

    ab_kernel<<<M_TOT / 128, 256>>>(x, WA, WB);
    scan_kernel<<<1, 256>>>();
    main_kernel<<<dim3(DD / 64, M_TOT / 128), 256>>>(x, WC, WD, bD, Wg, bg, out);
}

// round 3
// speedup vs baseline: 3.0321x; 3.0321x over previous
#include <cuda_runtime.h>
#include <cuda_bf16.h>
#include <math.h>
#include <stdint.h>

#define BB 16
#define SS 2048
#define DD 1024
#define NN 16
#define M_TOT (BB*SS)   // 32768 tokens

// ---------------- scratch (__device__ globals; no allocs allowed) ----------
__device__ __align__(256) float g_a[M_TOT*NN];
__device__ __align__(256) float g_b[M_TOT*NN];
__device__ __align__(256) float g_h[M_TOT*NN];
__device__ __align__(256) __nv_bfloat16 g_xhi[(size_t)M_TOT*DD];
__device__ __align__(256) __nv_bfloat16 g_xlo[(size_t)M_TOT*DD];
__device__ __align__(256) __nv_bfloat16 g_whi[2048*DD];
__device__ __align__(256) __nv_bfloat16 g_wlo[2048*DD];
__device__ float g_Ac[256*32];
__device__ float g_Bc[256*32];
__device__ float g_carry[256*32];

// ---------------- PTX helpers ----------------------------------------------
__device__ __forceinline__ uint32_t smem_u32(const void* p) {
    uint32_t a;
    asm("{ .reg .u64 t; cvta.to.shared.u64 t, %1; cvt.u32.u64 %0, t; }" : "=r"(a) : "l"(p));
    return a;
}
__device__ __forceinline__ void cp16(uint32_t dst, const void* src) {
    asm volatile("cp.async.cg.shared.global [%0], [%1], 16;" :: "r"(dst), "l"(src) : "memory");
}
#define CP_COMMIT() asm volatile("cp.async.commit_group;" ::: "memory")
#define CP_WAIT1()  asm volatile("cp.async.wait_group 1;" ::: "memory")
#define CP_WAIT0()  asm volatile("cp.async.wait_group 0;" ::: "memory")

__device__ __forceinline__ void ldsm4(uint32_t* r, uint32_t addr) {
    asm volatile("ldmatrix.sync.aligned.m8n8.x4.shared.b16 {%0,%1,%2,%3}, [%4];"
                 : "=r"(r[0]), "=r"(r[1]), "=r"(r[2]), "=r"(r[3]) : "r"(addr));
}
__device__ __forceinline__ void mma16816(float* d, const uint32_t* a, const uint32_t* b) {
    asm volatile("mma.sync.aligned.m16n8k16.row.col.f32.bf16.bf16.f32 "
                 "{%0,%1,%2,%3}, {%4,%5,%6,%7}, {%8,%9}, {%0,%1,%2,%3};"
                 : "+f"(d[0]), "+f"(d[1]), "+f"(d[2]), "+f"(d[3])
                 : "r"(a[0]), "r"(a[1]), "r"(a[2]), "r"(a[3]), "r"(b[0]), "r"(b[1]));
}

// ---------------------------------------------------------------------------
// Kernel 1: ab + x-split.  a=tanh(x@WA^T), b=x@WB^T, and write g_xhi/g_xlo.
// ---------------------------------------------------------------------------
__global__ __launch_bounds__(256) void ab_split_kernel(const float* __restrict__ x,
                                                       const float* __restrict__ WA,
                                                       const float* __restrict__ WB)
{
    __shared__ float Xs[128][33];
    __shared__ float Ws[32][33];
    const int tid = threadIdx.x;
    const int m0  = blockIdx.x * 128;
    const int otx = tid & 7;
    const int tty = tid >> 3;

    float acc[4][4] = {};

    for (int k0 = 0; k0 < DD; k0 += 32) {
        #pragma unroll
        for (int r = 0; r < 4; r++) {
            int idx = tid + r * 256;
            int t  = idx >> 3;
            int kv = idx & 7;
            size_t off = (size_t)(m0 + t) * DD + k0 + kv * 4;
            float4 v = *(const float4*)(x + off);
            Xs[t][kv*4+0] = v.x; Xs[t][kv*4+1] = v.y;
            Xs[t][kv*4+2] = v.z; Xs[t][kv*4+3] = v.w;
            float hx = __bfloat162float(__float2bfloat16_rn(v.x));
            float hy = __bfloat162float(__float2bfloat16_rn(v.y));
            float hz = __bfloat162float(__float2bfloat16_rn(v.z));
            float hw = __bfloat162float(__float2bfloat16_rn(v.w));
            __nv_bfloat162 hA = __floats2bfloat162_rn(hx, hy);
            __nv_bfloat162 hB = __floats2bfloat162_rn(hz, hw);
            __nv_bfloat162 lA = __floats2bfloat162_rn(v.x - hx, v.y - hy);
            __nv_bfloat162 lB = __floats2bfloat162_rn(v.z - hz, v.w - hw);
            uint2 hp, lp;
            hp.x = *(uint32_t*)&hA; hp.y = *(uint32_t*)&hB;
            lp.x = *(uint32_t*)&lA; lp.y = *(uint32_t*)&lB;
            *(uint2*)(g_xhi + off) = hp;
            *(uint2*)(g_xlo + off) = lp;
        }
        {
            int n  = tid >> 3;
            int kv = tid & 7;
            const float* Wsrc = (n < 16) ? (WA + (size_t)n * DD)
                                         : (WB + (size_t)(n - 16) * DD);
            float4 v = *(const float4*)(Wsrc + k0 + kv * 4);
            Ws[n][kv*4+0] = v.x; Ws[n][kv*4+1] = v.y;
            Ws[n][kv*4+2] = v.z; Ws[n][kv*4+3] = v.w;
        }
        __syncthreads();

        #pragma unroll
        for (int kk = 0; kk < 32; kk++) {
            float xr[4], wr[4];
            #pragma unroll
            for (int i = 0; i < 4; i++) xr[i] = Xs[tty*4 + i][kk];
            #pragma unroll
            for (int j = 0; j < 4; j++) wr[j] = Ws[otx*4 + j][kk];
            #pragma unroll
            for (int i = 0; i < 4; i++)
                #pragma unroll
                for (int j = 0; j < 4; j++)
                    acc[i][j] = fmaf(xr[i], wr[j], acc[i][j]);
        }
        __syncthreads();
    }

    #pragma unroll
    for (int i = 0; i < 4; i++) {
        int t = m0 + tty*4 + i;
        #pragma unroll
        for (int j = 0; j < 4; j++) {
            int n = otx*4 + j;
            if (n < 16) g_a[(size_t)t * NN + n]        = tanhf(acc[i][j]);
            else        g_b[(size_t)t * NN + (n - 16)] = acc[i][j];
        }
    }
}

// ---------------------------------------------------------------------------
// Kernel 2: weight split + reorder: row r = j*128+s (s<64 -> Wg, s>=64 -> WD)
// ---------------------------------------------------------------------------
__global__ __launch_bounds__(256) void wsplit_kernel(const float* __restrict__ Wg,
                                                     const float* __restrict__ WD)
{
    int idx = blockIdx.x * 256 + threadIdx.x;
    int r  = idx >> 8;
    int c4 = idx & 255;
    int jb = r >> 7, s = r & 127;
    const float* src = (s < 64) ? (Wg + (size_t)(jb*64 + s) * DD)
                                : (WD + (size_t)(jb*64 + s - 64) * DD);
    float4 v = ((const float4*)src)[c4];
    size_t off = (size_t)r * DD + c4 * 4;
    float hx = __bfloat162float(__float2bfloat16_rn(v.x));
    float hy = __bfloat162float(__float2bfloat16_rn(v.y));
    float hz = __bfloat162float(__float2bfloat16_rn(v.z));
    float hw = __bfloat162float(__float2bfloat16_rn(v.w));
    __nv_bfloat162 hA = __floats2bfloat162_rn(hx, hy);
    __nv_bfloat162 hB = __floats2bfloat162_rn(hz, hw);
    __nv_bfloat162 lA = __floats2bfloat162_rn(v.x - hx, v.y - hy);
    __nv_bfloat162 lB = __floats2bfloat162_rn(v.z - hz, v.w - hw);
    uint2 hp, lp;
    hp.x = *(uint32_t*)&hA; hp.y = *(uint32_t*)&hB;
    lp.x = *(uint32_t*)&lA; lp.y = *(uint32_t*)&lB;
    *(uint2*)(g_whi + off) = hp;
    *(uint2*)(g_wlo + off) = lp;
}

// ---------------------------------------------------------------------------
// Chunked parallel scan: 32 chunks of 64 steps, 256 chains
// ---------------------------------------------------------------------------
__global__ __launch_bounds__(256) void scan1_kernel()
{
    int id = blockIdx.x * 256 + threadIdx.x;          // 8192
    int n = id & 15, ch = (id >> 4) & 31, b = id >> 9;
    float A = 1.0f, h = 0.0f;
    size_t base = ((size_t)b * SS + ch * 64) * NN + n;
    #pragma unroll 4
    for (int i = 0; i < 64; i++) {
        float av = g_a[base + (size_t)i * NN];
        float bv = g_b[base + (size_t)i * NN];
        A *= av;
        h = fmaf(av, h, bv);
    }
    g_Ac[(b*16 + n)*32 + ch] = A;
    g_Bc[(b*16 + n)*32 + ch] = h;
}
__global__ __launch_bounds__(256) void scan2_kernel()
{
    int chain = threadIdx.x;                          // 256
    float carry = 0.0f;
    #pragma unroll
    for (int c = 0; c < 32; c++) {
        g_carry[chain*32 + c] = carry;
        carry = fmaf(g_Ac[chain*32 + c], carry, g_Bc[chain*32 + c]);
    }
}
__global__ __launch_bounds__(256) void scan3_kernel()
{
    int id = blockIdx.x * 256 + threadIdx.x;
    int n = id & 15, ch = (id >> 4) & 31, b = id >> 9;
    float h = g_carry[(b*16 + n)*32 + ch];
    size_t base = ((size_t)b * SS + ch * 64) * NN + n;
    #pragma unroll 4
    for (int i = 0; i < 64; i++) {
        size_t idx = base + (size_t)i * NN;
        h = fmaf(g_a[idx], h, g_b[idx]);
        g_h[idx] = h;
    }
}

// ---------------------------------------------------------------------------
// Main mma.sync bf16 GEMM: CTA 128x128, BK=64, K_eff = 3*1024 (split-bf16),
// double-buffered cp.async, fused gating epilogue.
// Smem row layout: 64 bf16 (128B) + 16B pad -> 144B stride (ldmatrix
// conflict-free since 144 mod 128 = 16 walks all 8 bank groups).
// ---------------------------------------------------------------------------
#define ROWB    144
#define ATILE   (128*ROWB)           // 18432
#define BUFSZ   (2*ATILE)            // 36864 per stage (A + W)
#define HS_OFF  (2*BUFSZ)            // 73728
#define WCS_OFF (HS_OFF + 128*17*4)  // 82432
#define BG_OFF  (WCS_OFF + 64*17*4)  // 86784
#define BD_OFF  (BG_OFF + 256)
#define SMEM_BYTES (BD_OFF + 256)
#define NCHUNK 48

__device__ __forceinline__ void load_chunk(uint32_t sbase, int c, int m0, int j, int tid)
{
    int phs = c >> 4;                 // 0: xhi*whi, 1: xhi*wlo, 2: xlo*whi
    int kc  = (c & 15) * 64;
    const __nv_bfloat16* As = (phs == 2) ? g_xlo : g_xhi;
    const __nv_bfloat16* Ws = (phs == 1) ? g_wlo : g_whi;
    uint32_t buf = sbase + (c & 1) * BUFSZ;
    #pragma unroll
    for (int i = 0; i < 8; i++) {
        int u = tid + i * 256;
        int region = u >> 10;         // 0 = A, 1 = W
        int v = u & 1023;
        int row = v >> 3, c16 = v & 7;
        uint32_t dst = buf + region * ATILE + row * ROWB + c16 * 16;
        const __nv_bfloat16* src = region == 0
            ? As + (size_t)(m0 + row) * DD + kc + c16 * 8
            : Ws + (size_t)(j * 128 + row) * DD + kc + c16 * 8;
        cp16(dst, src);
    }
    CP_COMMIT();
}

__global__ __launch_bounds__(256, 2) void main_kernel(const float* __restrict__ WC,
                                                      const float* __restrict__ bD,
                                                      const float* __restrict__ bg,
                                                      float* __restrict__ out)
{
    extern __shared__ char smem[];
    uint32_t sbase = smem_u32(smem);
    const int tid    = threadIdx.x;
    const int lane   = tid & 31;
    const int wid    = tid >> 5;
    const int warp_m = wid & 1;       // 2 m-warps (64 rows each)
    const int warp_n = wid >> 1;      // 4 n-warps (32 cols each)
    const int j  = blockIdx.x;        // e-block (16)
    const int m0 = blockIdx.y * 128;  // token base

    // epilogue constants (separate smem region; loaded up front)
    float* Hs  = (float*)(smem + HS_OFF);    // [128][17]
    float* WCs = (float*)(smem + WCS_OFF);   // [64][17]
    float* BGs = (float*)(smem + BG_OFF);
    float* BDs = (float*)(smem + BD_OFF);
    {
        #pragma unroll
        for (int r = 0; r < 2; r++) {        // Hs: 512 float4
            int u = tid + r * 256;
            int t = u >> 2, kv = u & 3;
            float4 v = *(const float4*)(g_h + (size_t)(m0 + t) * NN + kv * 4);
            Hs[t*17 + kv*4+0] = v.x; Hs[t*17 + kv*4+1] = v.y;
            Hs[t*17 + kv*4+2] = v.z; Hs[t*17 + kv*4+3] = v.w;
        }
        int e = tid >> 2, kv = tid & 3;      // WCs: 256 float4
        float4 v = *(const float4*)(WC + (size_t)(j*64 + e) * NN + kv * 4);
        WCs[e*17 + kv*4+0] = v.x; WCs[e*17 + kv*4+1] = v.y;
        WCs[e*17 + kv*4+2] = v.z; WCs[e*17 + kv*4+3] = v.w;
        if (tid < 64) { BGs[tid] = bg[j*64 + tid]; BDs[tid] = bD[j*64 + tid]; }
    }

    float d[4][4][4] = {};   // [mi][ni][frag]

    // per-lane ldmatrix base offsets (within a stage buffer)
    const uint32_t aOff = (uint32_t)((warp_m*64 + (lane & 15)) * ROWB + (lane >> 4) * 16);
    const uint32_t bOff = (uint32_t)(ATILE +
                          (warp_n*32 + ((lane >> 4) << 3) + (lane & 7)) * ROWB +
                          ((lane >> 3) & 1) * 16);

    load_chunk(sbase, 0, m0, j, tid);
    load_chunk(sbase, 1, m0, j, tid);

    for (int c = 0; c < NCHUNK; c++) {
        if (c < NCHUNK - 1) CP_WAIT1(); else CP_WAIT0();
        __syncthreads();

        uint32_t buf = sbase + (c & 1) * BUFSZ;
        uint32_t aP = buf + aOff;
        uint32_t bP = buf + bOff;
        #pragma unroll
        for (int kk = 0; kk < 4; kk++) {
            uint32_t a[4][4], b[8];
            #pragma unroll
            for (int mi = 0; mi < 4; mi++)
                ldsm4(a[mi], aP + mi * (16*ROWB) + kk * 32);
            ldsm4(&b[0], bP + kk * 32);                 // n-tiles 0,1
            ldsm4(&b[4], bP + 16*ROWB + kk * 32);       // n-tiles 2,3
            #pragma unroll
            for (int mi = 0; mi < 4; mi++)
                #pragma unroll
                for (int ni = 0; ni < 4; ni++)
                    mma16816(d[mi][ni], a[mi], &b[ni*2]);
        }
        __syncthreads();
        if (c + 2 < NCHUNK) load_chunk(sbase, c + 2, m0, j, tid);
    }

    // ---- epilogue: frags -> smem Cs[128][132], then gate/skip fuse ----
    float* Cs = (float*)smem;   // reuses buffer region (67584 B <= 73728)
    __syncthreads();
    #pragma unroll
    for (int mi = 0; mi < 4; mi++) {
        #pragma unroll
        for (int ni = 0; ni < 4; ni++) {
            int row0 = warp_m*64 + mi*16 + (lane >> 2);
            int col  = warp_n*32 + ni*8  + (lane & 3) * 2;
            *(float2*)&Cs[row0*132 + col]     = make_float2(d[mi][ni][0], d[mi][ni][1]);
            *(float2*)&Cs[(row0+8)*132 + col] = make_float2(d[mi][ni][2], d[mi][ni][3]);
        }
    }
    __syncthreads();

    #pragma unroll 4
    for (int it = 0; it < 32; it++) {
        int idx = it * 256 + tid;       // 8192 outputs
        int t = idx >> 6, s = idx & 63;
        float y = 0.0f;
        #pragma unroll
        for (int n = 0; n < 16; n++)
            y = fmaf(Hs[t*17 + n], WCs[s*17 + n], y);
        float c1 = Cs[t*132 + s]      + BGs[s];
        float c2 = Cs[t*132 + 64 + s] + BDs[s];
        float gv = 1.0f / (1.0f + __expf(-c1));
        out[(size_t)(m0 + t) * DD + j*64 + s] = y * gv + c2 * (1.0f - gv);
    }
}

// ---------------------------------------------------------------------------
extern "C" void kernel_launch(void* const* d_in, const int* in_sizes, int n_in,
                              void* d_out, int out_size)
{
    const float* x  = (const float*)d_in[0];
    const float* WA = (const float*)d_in[1];
    const float* WB = (const float*)d_in[2];
    const float* WC = (const float*)d_in[3];
    const float* WD = (const float*)d_in[4];
    const float* bD = (const float*)d_in[5];
    const float* Wg = (const float*)d_in[6];
    const float* bg = (const float*)d_in[7];
    float* out = (float*)d_out;

    cudaFuncSetAttribute(main_kernel,
                         cudaFuncAttributeMaxDynamicSharedMemorySize, SMEM_BYTES);

    ab_split_kernel<<<M_TOT / 128, 256>>>(x, WA, WB);
    wsplit_kernel<<<2048, 256>>>(Wg, WD);
    scan1_kernel<<<32, 256>>>();
    scan2_kernel<<<1, 256>>>();
    scan3_kernel<<<32, 256>>>();
    main_kernel<<<dim3(16, 256), 256, SMEM_BYTES>>>(WC, bD, bg, out);
}

// round 5
// speedup vs baseline: 4.8984x; 1.6155x over previous
#include <cuda_runtime.h>
#include <cuda_fp16.h>
#include <math.h>
#include <stdint.h>

#define BB 16
#define SS 2048
#define DD 1024
#define NN 16
#define M_TOT (BB*SS)   // 32768 tokens

// ---------------- scratch (__device__ globals; no allocs allowed) ----------
__device__ __align__(256) float g_a[M_TOT*NN];
__device__ __align__(256) float g_b[M_TOT*NN];
__device__ __align__(256) float g_h[M_TOT*NN];
__device__ __align__(256) __half g_xhi[(size_t)M_TOT*DD];
__device__ __align__(256) __half g_xlo[(size_t)M_TOT*DD];
__device__ __align__(256) __half g_whi[2048*DD];
__device__ float g_Ac[256*32];
__device__ float g_Bc[256*32];
__device__ float g_carry[256*32];

// ---------------- PTX helpers ----------------------------------------------
__device__ __forceinline__ uint32_t smem_u32(const void* p) {
    uint32_t a;
    asm("{ .reg .u64 t; cvta.to.shared.u64 t, %1; cvt.u32.u64 %0, t; }" : "=r"(a) : "l"(p));
    return a;
}
__device__ __forceinline__ void cp16(uint32_t dst, const void* src) {
    asm volatile("cp.async.cg.shared.global [%0], [%1], 16;" :: "r"(dst), "l"(src) : "memory");
}
#define CP_COMMIT() asm volatile("cp.async.commit_group;" ::: "memory")
#define CP_WAIT1()  asm volatile("cp.async.wait_group 1;" ::: "memory")
#define CP_WAIT0()  asm volatile("cp.async.wait_group 0;" ::: "memory")

__device__ __forceinline__ void ldsm4(uint32_t* r, uint32_t addr) {
    asm volatile("ldmatrix.sync.aligned.m8n8.x4.shared.b16 {%0,%1,%2,%3}, [%4];"
                 : "=r"(r[0]), "=r"(r[1]), "=r"(r[2]), "=r"(r[3]) : "r"(addr));
}
__device__ __forceinline__ void mma16816(float* d, const uint32_t* a, const uint32_t* b) {
    asm volatile("mma.sync.aligned.m16n8k16.row.col.f32.f16.f16.f32 "
                 "{%0,%1,%2,%3}, {%4,%5,%6,%7}, {%8,%9}, {%0,%1,%2,%3};"
                 : "+f"(d[0]), "+f"(d[1]), "+f"(d[2]), "+f"(d[3])
                 : "r"(a[0]), "r"(a[1]), "r"(a[2]), "r"(a[3]), "r"(b[0]), "r"(b[1]));
}

// ---------------------------------------------------------------------------
// Kernel 1: ab + x-split (fp16 hi/lo).
// ---------------------------------------------------------------------------
__global__ __launch_bounds__(256) void ab_split_kernel(const float* __restrict__ x,
                                                       const float* __restrict__ WA,
                                                       const float* __restrict__ WB)
{
    __shared__ float Xs[128][33];
    __shared__ float Ws[32][33];
    const int tid = threadIdx.x;
    const int m0  = blockIdx.x * 128;
    const int otx = tid & 7;
    const int tty = tid >> 3;

    float acc[4][4] = {};

    for (int k0 = 0; k0 < DD; k0 += 32) {
        #pragma unroll
        for (int r = 0; r < 4; r++) {
            int idx = tid + r * 256;
            int t  = idx >> 3;
            int kv = idx & 7;
            size_t off = (size_t)(m0 + t) * DD + k0 + kv * 4;
            float4 v = *(const float4*)(x + off);
            Xs[t][kv*4+0] = v.x; Xs[t][kv*4+1] = v.y;
            Xs[t][kv*4+2] = v.z; Xs[t][kv*4+3] = v.w;
            __half hx = __float2half_rn(v.x), hy = __float2half_rn(v.y);
            __half hz = __float2half_rn(v.z), hw = __float2half_rn(v.w);
            __half2 hA = __halves2half2(hx, hy), hB = __halves2half2(hz, hw);
            __half2 lA = __floats2half2_rn(v.x - __half2float(hx), v.y - __half2float(hy));
            __half2 lB = __floats2half2_rn(v.z - __half2float(hz), v.w - __half2float(hw));
            uint2 hp, lp;
            hp.x = *(uint32_t*)&hA; hp.y = *(uint32_t*)&hB;
            lp.x = *(uint32_t*)&lA; lp.y = *(uint32_t*)&lB;
            *(uint2*)(g_xhi + off) = hp;
            *(uint2*)(g_xlo + off) = lp;
        }
        {
            int n  = tid >> 3;
            int kv = tid & 7;
            const float* Wsrc = (n < 16) ? (WA + (size_t)n * DD)
                                         : (WB + (size_t)(n - 16) * DD);
            float4 v = *(const float4*)(Wsrc + k0 + kv * 4);
            Ws[n][kv*4+0] = v.x; Ws[n][kv*4+1] = v.y;
            Ws[n][kv*4+2] = v.z; Ws[n][kv*4+3] = v.w;
        }
        __syncthreads();

        #pragma unroll
        for (int kk = 0; kk < 32; kk++) {
            float xr[4], wr[4];
            #pragma unroll
            for (int i = 0; i < 4; i++) xr[i] = Xs[tty*4 + i][kk];
            #pragma unroll
            for (int j = 0; j < 4; j++) wr[j] = Ws[otx*4 + j][kk];
            #pragma unroll
            for (int i = 0; i < 4; i++)
                #pragma unroll
                for (int j = 0; j < 4; j++)
                    acc[i][j] = fmaf(xr[i], wr[j], acc[i][j]);
        }
        __syncthreads();
    }

    #pragma unroll
    for (int i = 0; i < 4; i++) {
        int t = m0 + tty*4 + i;
        #pragma unroll
        for (int j = 0; j < 4; j++) {
            int n = otx*4 + j;
            if (n < 16) g_a[(size_t)t * NN + n]        = tanhf(acc[i][j]);
            else        g_b[(size_t)t * NN + (n - 16)] = acc[i][j];
        }
    }
}

// ---------------------------------------------------------------------------
// Kernel 2: weight fp16 convert + reorder: row r = j*128+s (s<64 Wg, else WD)
// ---------------------------------------------------------------------------
__global__ __launch_bounds__(256) void wsplit_kernel(const float* __restrict__ Wg,
                                                     const float* __restrict__ WD)
{
    int idx = blockIdx.x * 256 + threadIdx.x;     // 2048 rows * 256 float4
    int r  = idx >> 8;
    int c4 = idx & 255;
    int jb = r >> 7, s = r & 127;
    const float* src = (s < 64) ? (Wg + (size_t)(jb*64 + s) * DD)
                                : (WD + (size_t)(jb*64 + s - 64) * DD);
    float4 v = ((const float4*)src)[c4];
    __half2 hA = __floats2half2_rn(v.x, v.y);
    __half2 hB = __floats2half2_rn(v.z, v.w);
    uint2 hp;
    hp.x = *(uint32_t*)&hA; hp.y = *(uint32_t*)&hB;
    *(uint2*)(g_whi + (size_t)r * DD + c4 * 4) = hp;
}

// ---------------------------------------------------------------------------
// Chunked parallel scan
// ---------------------------------------------------------------------------
__global__ __launch_bounds__(256) void scan1_kernel()
{
    int id = blockIdx.x * 256 + threadIdx.x;
    int n = id & 15, ch = (id >> 4) & 31, b = id >> 9;
    float A = 1.0f, h = 0.0f;
    size_t base = ((size_t)b * SS + ch * 64) * NN + n;
    #pragma unroll 4
    for (int i = 0; i < 64; i++) {
        float av = g_a[base + (size_t)i * NN];
        float bv = g_b[base + (size_t)i * NN];
        A *= av;
        h = fmaf(av, h, bv);
    }
    g_Ac[(b*16 + n)*32 + ch] = A;
    g_Bc[(b*16 + n)*32 + ch] = h;
}
__global__ __launch_bounds__(256) void scan2_kernel()
{
    extern __shared__ float s2[];                 // sA[256*33] | sB[256*33]
    float* sA = s2;
    float* sB = s2 + 256*33;
    const int tid = threadIdx.x;
    #pragma unroll
    for (int i = 0; i < 32; i++) {
        int idx = i * 256 + tid;            // 8192
        int chain = idx >> 5, c = idx & 31;
        sA[chain*33 + c] = g_Ac[idx];
        sB[chain*33 + c] = g_Bc[idx];
    }
    __syncthreads();
    float carry = 0.0f;
    #pragma unroll
    for (int c = 0; c < 32; c++) {
        g_carry[tid*32 + c] = carry;
        carry = fmaf(sA[tid*33 + c], carry, sB[tid*33 + c]);
    }
}
__global__ __launch_bounds__(256) void scan3_kernel()
{
    int id = blockIdx.x * 256 + threadIdx.x;
    int n = id & 15, ch = (id >> 4) & 31, b = id >> 9;
    float h = g_carry[(b*16 + n)*32 + ch];
    size_t base = ((size_t)b * SS + ch * 64) * NN + n;
    #pragma unroll 4
    for (int i = 0; i < 64; i++) {
        size_t idx = base + (size_t)i * NN;
        h = fmaf(g_a[idx], h, g_b[idx]);
        g_h[idx] = h;
    }
}

// ---------------------------------------------------------------------------
// Main mma.sync fp16 GEMM: CTA 128x128, BK=64, K_eff = 2*1024 (2-term fp16),
// 3-stage cp.async ring, XOR-swizzled smem (128B rows), fused gating epilogue.
// ---------------------------------------------------------------------------
#define STAGE   32768                 // A tile 16384 + W tile 16384
#define HS_OFF  (3*STAGE)             // 98304
#define WCS_OFF (HS_OFF + 128*17*4)   // 107008
#define BG_OFF  (WCS_OFF + 64*17*4)   // 111360
#define BD_OFF  (BG_OFF + 256)        // 111616
#define SMEM_BYTES (BD_OFF + 256)     // 111872
#define NCHUNK 32

__device__ __forceinline__ void load_chunk(uint32_t sbase, int c, int m0, int j, int tid)
{
    const __half* As = (c >> 4) ? g_xlo : g_xhi;   // phase 0: hi, 1: lo
    int kc = (c & 15) * 64;
    uint32_t buf = sbase + (c % 3) * STAGE;
    #pragma unroll
    for (int i = 0; i < 8; i++) {
        int u = tid + i * 256;
        int region = u >> 10;          // 0 = A, 1 = W
        int v = u & 1023;
        int row = v >> 3, c16 = v & 7;
        uint32_t dst = buf + region * 16384 + row * 128 + ((c16 ^ (row & 7)) * 16);
        const __half* src = region == 0
            ? As + (size_t)(m0 + row) * DD + kc + c16 * 8
            : g_whi + (size_t)(j * 128 + row) * DD + kc + c16 * 8;
        cp16(dst, src);
    }
    CP_COMMIT();
}

__global__ __launch_bounds__(256, 2) void main_kernel(const float* __restrict__ WC,
                                                      const float* __restrict__ bD,
                                                      const float* __restrict__ bg,
                                                      float* __restrict__ out)
{
    extern __shared__ char smem[];
    uint32_t sbase = smem_u32(smem);
    const int tid    = threadIdx.x;
    const int lane   = tid & 31;
    const int wid    = tid >> 5;
    const int warp_m = wid & 1;       // 2 m-warps (64 rows each)
    const int warp_n = wid >> 1;      // 4 n-warps (32 cols each)
    const int j  = blockIdx.x;        // e-block (16)
    const int m0 = blockIdx.y * 128;  // token base

    // epilogue constants
    float* Hs  = (float*)(smem + HS_OFF);    // [128][17]
    float* WCs = (float*)(smem + WCS_OFF);   // [64][17]
    float* BGs = (float*)(smem + BG_OFF);
    float* BDs = (float*)(smem + BD_OFF);
    {
        #pragma unroll
        for (int r = 0; r < 2; r++) {
            int u = tid + r * 256;
            int t = u >> 2, kv = u & 3;
            float4 v = *(const float4*)(g_h + (size_t)(m0 + t) * NN + kv * 4);
            Hs[t*17 + kv*4+0] = v.x; Hs[t*17 + kv*4+1] = v.y;
            Hs[t*17 + kv*4+2] = v.z; Hs[t*17 + kv*4+3] = v.w;
        }
        int e = tid >> 2, kv = tid & 3;
        float4 v = *(const float4*)(WC + (size_t)(j*64 + e) * NN + kv * 4);
        WCs[e*17 + kv*4+0] = v.x; WCs[e*17 + kv*4+1] = v.y;
        WCs[e*17 + kv*4+2] = v.z; WCs[e*17 + kv*4+3] = v.w;
        if (tid < 64) { BGs[tid] = bg[j*64 + tid]; BDs[tid] = bD[j*64 + tid]; }
    }

    float d[4][4][4] = {};

    // per-lane base offsets (swizzle mask = lane&7 for both A and B)
    const uint32_t lh    = lane & 7;
    const uint32_t aRow  = (uint32_t)(warp_m*64 + (lane & 15));
    const uint32_t aHalf = (uint32_t)(lane >> 4);
    const uint32_t aBase = aRow * 128;
    const uint32_t bRow  = (uint32_t)(warp_n*32 + ((lane >> 4) << 3) + lh);
    const uint32_t bHalf = (uint32_t)((lane >> 3) & 1);
    const uint32_t bBase = 16384 + bRow * 128;

    load_chunk(sbase, 0, m0, j, tid);
    load_chunk(sbase, 1, m0, j, tid);

    for (int c = 0; c < NCHUNK; c++) {
        if (c < NCHUNK - 2) CP_WAIT1(); else CP_WAIT0();
        __syncthreads();
        if (c + 2 < NCHUNK) load_chunk(sbase, c + 2, m0, j, tid);

        uint32_t buf = sbase + (c % 3) * STAGE;
        #pragma unroll
        for (int kk = 0; kk < 4; kk++) {
            uint32_t a[4][4], b[8];
            uint32_t aC = ((uint32_t)(kk*2) + aHalf) ^ lh;
            uint32_t bC = ((uint32_t)(kk*2) + bHalf) ^ lh;
            #pragma unroll
            for (int mi = 0; mi < 4; mi++)
                ldsm4(a[mi], buf + aBase + mi * 2048 + aC * 16);
            ldsm4(&b[0], buf + bBase + bC * 16);
            ldsm4(&b[4], buf + bBase + 2048 + bC * 16);
            #pragma unroll
            for (int mi = 0; mi < 4; mi++)
                #pragma unroll
                for (int ni = 0; ni < 4; ni++)
                    mma16816(d[mi][ni], a[mi], &b[ni*2]);
        }
    }

    // ---- epilogue: frags -> smem Cs[128][132], then gate/skip fuse ----
    float* Cs = (float*)smem;   // 67584 B, reuses stage region
    __syncthreads();
    #pragma unroll
    for (int mi = 0; mi < 4; mi++) {
        #pragma unroll
        for (int ni = 0; ni < 4; ni++) {
            int row0 = warp_m*64 + mi*16 + (lane >> 2);
            int col  = warp_n*32 + ni*8  + (lane & 3) * 2;
            *(float2*)&Cs[row0*132 + col]     = make_float2(d[mi][ni][0], d[mi][ni][1]);
            *(float2*)&Cs[(row0+8)*132 + col] = make_float2(d[mi][ni][2], d[mi][ni][3]);
        }
    }
    __syncthreads();

    #pragma unroll 4
    for (int it = 0; it < 32; it++) {
        int idx = it * 256 + tid;       // 8192 outputs
        int t = idx >> 6, s = idx & 63;
        float y = 0.0f;
        #pragma unroll
        for (int n = 0; n < 16; n++)
            y = fmaf(Hs[t*17 + n], WCs[s*17 + n], y);
        float c1 = Cs[t*132 + s]      + BGs[s];
        float c2 = Cs[t*132 + 64 + s] + BDs[s];
        float gv = 1.0f / (1.0f + __expf(-c1));
        out[(size_t)(m0 + t) * DD + j*64 + s] = y * gv + c2 * (1.0f - gv);
    }
}

// ---------------------------------------------------------------------------
extern "C" void kernel_launch(void* const* d_in, const int* in_sizes, int n_in,
                              void* d_out, int out_size)
{
    const float* x  = (const float*)d_in[0];
    const float* WA = (const float*)d_in[1];
    const float* WB = (const float*)d_in[2];
    const float* WC = (const float*)d_in[3];
    const float* WD = (const float*)d_in[4];
    const float* bD = (const float*)d_in[5];
    const float* Wg = (const float*)d_in[6];
    const float* bg = (const float*)d_in[7];
    float* out = (float*)d_out;

    cudaFuncSetAttribute(main_kernel,
                         cudaFuncAttributeMaxDynamicSharedMemorySize, SMEM_BYTES);
    cudaFuncSetAttribute(scan2_kernel,
                         cudaFuncAttributeMaxDynamicSharedMemorySize, 2*256*33*4);

    ab_split_kernel<<<M_TOT / 128, 256>>>(x, WA, WB);
    wsplit_kernel<<<2048, 256>>>(Wg, WD);
    scan1_kernel<<<32, 256>>>();
    scan2_kernel<<<1, 256, 2*256*33*4>>>();
    scan3_kernel<<<32, 256>>>();
    main_kernel<<<dim3(16, 256), 256, SMEM_BYTES>>>(WC, bD, bg, out);
}

// round 7
// speedup vs baseline: 5.6687x; 1.1573x over previous
#include <cuda_runtime.h>
#include <cuda_fp16.h>
#include <math.h>
#include <stdint.h>

#define BB 16
#define SS 2048
#define DD 1024
#define NN 16
#define M_TOT (BB*SS)   // 32768 tokens

// ---------------- scratch (__device__ globals) ------------------------------
__device__ __align__(256) float g_a[M_TOT*NN];
__device__ __align__(256) float g_b[M_TOT*NN];
__device__ __align__(256) __half g_hhi[M_TOT*NN];
__device__ __align__(256) __half g_hlo[M_TOT*NN];
__device__ __align__(256) __half g_xhi[(size_t)M_TOT*DD];
__device__ __align__(256) __half g_xlo[(size_t)M_TOT*DD];
__device__ __align__(256) __half g_whi[2048*DD];
__device__ __align__(256) __half g_wabhi[32*DD];
__device__ __align__(256) __half g_wablo[32*DD];
__device__ __align__(256) __half g_wchi[DD*NN];
__device__ __align__(256) __half g_wclo[DD*NN];
__device__ float g_Ac[256*32];
__device__ float g_Bc[256*32];
__device__ float g_carry[256*32];

// ---------------- PTX helpers ----------------------------------------------
__device__ __forceinline__ uint32_t smem_u32(const void* p) {
    uint32_t a;
    asm("{ .reg .u64 t; cvta.to.shared.u64 t, %1; cvt.u32.u64 %0, t; }" : "=r"(a) : "l"(p));
    return a;
}
__device__ __forceinline__ void cp16(uint32_t dst, const void* src) {
    asm volatile("cp.async.cg.shared.global [%0], [%1], 16;" :: "r"(dst), "l"(src) : "memory");
}
#define CP_COMMIT() asm volatile("cp.async.commit_group;" ::: "memory")
#define CP_WAIT1()  asm volatile("cp.async.wait_group 1;" ::: "memory")
#define CP_WAIT0()  asm volatile("cp.async.wait_group 0;" ::: "memory")

__device__ __forceinline__ void ldsm4(uint32_t* r, uint32_t addr) {
    asm volatile("ldmatrix.sync.aligned.m8n8.x4.shared.b16 {%0,%1,%2,%3}, [%4];"
                 : "=r"(r[0]), "=r"(r[1]), "=r"(r[2]), "=r"(r[3]) : "r"(addr));
}
__device__ __forceinline__ void mma16816(float* d, const uint32_t* a, const uint32_t* b) {
    asm volatile("mma.sync.aligned.m16n8k16.row.col.f32.f16.f16.f32 "
                 "{%0,%1,%2,%3}, {%4,%5,%6,%7}, {%8,%9}, {%0,%1,%2,%3};"
                 : "+f"(d[0]), "+f"(d[1]), "+f"(d[2]), "+f"(d[3])
                 : "r"(a[0]), "r"(a[1]), "r"(a[2]), "r"(a[3]), "r"(b[0]), "r"(b[1]));
}

// ---------------------------------------------------------------------------
// wsplit: main weight fp16: row r = jb*128+s (s<64 Wg, else WD)
// ---------------------------------------------------------------------------
__global__ __launch_bounds__(256) void wsplit_kernel(const float* __restrict__ Wg,
                                                     const float* __restrict__ WD)
{
    int idx = blockIdx.x * 256 + threadIdx.x;     // 2048 rows * 256 float4
    int r  = idx >> 8;
    int c4 = idx & 255;
    int jb = r >> 7, s = r & 127;
    const float* src = (s < 64) ? (Wg + (size_t)(jb*64 + s) * DD)
                                : (WD + (size_t)(jb*64 + s - 64) * DD);
    float4 v = ((const float4*)src)[c4];
    __half2 hA = __floats2half2_rn(v.x, v.y);
    __half2 hB = __floats2half2_rn(v.z, v.w);
    uint2 hp;
    hp.x = *(uint32_t*)&hA; hp.y = *(uint32_t*)&hB;
    *(uint2*)(g_whi + (size_t)r * DD + c4 * 4) = hp;
}

// ---------------------------------------------------------------------------
// wprep: WA/WB hi/lo (32x1024) and WC hi/lo (1024x16)
// ---------------------------------------------------------------------------
__global__ __launch_bounds__(256) void wprep_kernel(const float* __restrict__ WA,
                                                    const float* __restrict__ WB,
                                                    const float* __restrict__ WC)
{
    int id = blockIdx.x * 256 + threadIdx.x;      // 192 blocks -> 49152
    float v;
    if (id < 32768) {
        int r = id >> 10, c = id & 1023;
        v = (r < 16) ? WA[(size_t)r * DD + c] : WB[(size_t)(r - 16) * DD + c];
        __half h = __float2half_rn(v);
        g_wabhi[id] = h;
        g_wablo[id] = __float2half_rn(v - __half2float(h));
    } else {
        int i2 = id - 32768;                      // WC: 1024*16
        v = WC[i2];
        __half h = __float2half_rn(v);
        g_wchi[i2] = h;
        g_wclo[i2] = __float2half_rn(v - __half2float(h));
    }
}

// ---------------------------------------------------------------------------
// prep: read x once -> write xhi/xlo; compute a=tanh(x@WA^T), b=x@WB^T via
// 3-term fp16 HMMA (xhi*whi + xhi*wlo + xlo*whi).
// ---------------------------------------------------------------------------
#define PXF 0
#define PXH 34816
#define PXL 51200
#define PWH 67584
#define PWL 71680
#define PREP_SMEM 75776

__global__ __launch_bounds__(256) void prep_kernel(const float* __restrict__ x)
{
    extern __shared__ char smem[];
    uint32_t sb = smem_u32(smem);
    const int tid  = threadIdx.x;
    const int lane = tid & 31;
    const int wid  = tid >> 5;
    const int m0   = blockIdx.x * 128;
    const uint32_t lh = lane & 7;

    float acc[4][4] = {};

    for (int c = 0; c < 16; c++) {
        int kc = c * 64;
        // x fp32 tile: 128 rows x 64 -> 2048 cp16 (pad stride 272B)
        #pragma unroll
        for (int i = 0; i < 8; i++) {
            int u = tid + i * 256;
            int row = u >> 4, c4 = u & 15;
            cp16(sb + PXF + row * 272 + c4 * 16,
                 x + (size_t)(m0 + row) * DD + kc + c4 * 4);
        }
        // WA/WB hi+lo tiles: 32 rows x 64 halves each -> 512 cp16
        #pragma unroll
        for (int i = 0; i < 2; i++) {
            int u = tid + i * 256;
            int sel = u >> 8, v = u & 255;
            int row = v >> 3, c16 = v & 7;
            const __half* src = (sel == 0 ? g_wabhi : g_wablo) + (size_t)row * DD + kc + c16 * 8;
            cp16(sb + (sel == 0 ? PWH : PWL) + row * 128 + ((c16 ^ (row & 7)) << 4), src);
        }
        CP_COMMIT();
        CP_WAIT0();
        __syncthreads();

        // convert fp32 -> hi/lo, write smem (swizzled) + gmem
        #pragma unroll
        for (int i = 0; i < 8; i++) {
            int u = tid + i * 256;
            int row = u >> 4;
            int q   = u & 15;            // float4 index within row
            float4 v = *(const float4*)(smem + PXF + row * 272 + q * 16);
            __half hx = __float2half_rn(v.x), hy = __float2half_rn(v.y);
            __half hz = __float2half_rn(v.z), hw = __float2half_rn(v.w);
            __half2 hA = __halves2half2(hx, hy), hB = __halves2half2(hz, hw);
            __half2 lA = __floats2half2_rn(v.x - __half2float(hx), v.y - __half2float(hy));
            __half2 lB = __floats2half2_rn(v.z - __half2float(hz), v.w - __half2float(hw));
            uint2 hp, lp;
            hp.x = *(uint32_t*)&hA; hp.y = *(uint32_t*)&hB;
            lp.x = *(uint32_t*)&lA; lp.y = *(uint32_t*)&lB;
            int c16 = q >> 1;
            uint32_t soff = row * 128 + (((uint32_t)c16 ^ (row & 7)) << 4) + (q & 1) * 8;
            *(uint2*)(smem + PXH + soff) = hp;
            *(uint2*)(smem + PXL + soff) = lp;
            size_t goff = (size_t)(m0 + row) * DD + kc + q * 4;
            *(uint2*)(g_xhi + goff) = hp;
            *(uint2*)(g_xlo + goff) = lp;
        }
        __syncthreads();

        // HMMA: warp tile 16 x 32
        const uint32_t aBase = (uint32_t)((wid * 16 + (lane & 15)) * 128);
        const uint32_t bRow  = (uint32_t)(((lane >> 4) << 3) + lh);
        #pragma unroll
        for (int kk = 0; kk < 4; kk++) {
            uint32_t aSw = (((uint32_t)(kk*2) + (lane >> 4)) ^ lh) << 4;
            uint32_t bSw = (((uint32_t)(kk*2) + ((lane >> 3) & 1)) ^ lh) << 4;
            uint32_t ah[4], al[4], bh[8], bl[8];
            ldsm4(ah, sb + PXH + aBase + aSw);
            ldsm4(al, sb + PXL + aBase + aSw);
            ldsm4(&bh[0], sb + PWH + bRow * 128 + bSw);
            ldsm4(&bh[4], sb + PWH + (bRow + 16) * 128 + bSw);
            ldsm4(&bl[0], sb + PWL + bRow * 128 + bSw);
            ldsm4(&bl[4], sb + PWL + (bRow + 16) * 128 + bSw);
            #pragma unroll
            for (int ni = 0; ni < 4; ni++) {
                mma16816(acc[ni], ah, &bh[ni*2]);
                mma16816(acc[ni], ah, &bl[ni*2]);
                mma16816(acc[ni], al, &bh[ni*2]);
            }
        }
        __syncthreads();
    }

    // write a (tanh) / b
    #pragma unroll
    for (int ni = 0; ni < 4; ni++) {
        #pragma unroll
        for (int fr = 0; fr < 4; fr++) {
            int row = m0 + wid*16 + (lane >> 2) + (fr >> 1) * 8;
            int col = ni*8 + (lane & 3) * 2 + (fr & 1);
            float v = acc[ni][fr];
            if (col < 16) g_a[(size_t)row * NN + col]        = tanhf(v);
            else          g_b[(size_t)row * NN + (col - 16)] = v;
        }
    }
}

// ---------------------------------------------------------------------------
// Chunked parallel scan; scan3 emits fp16 hi/lo of h
// ---------------------------------------------------------------------------
__global__ __launch_bounds__(256) void scan1_kernel()
{
    int id = blockIdx.x * 256 + threadIdx.x;
    int n = id & 15, ch = (id >> 4) & 31, b = id >> 9;
    float A = 1.0f, h = 0.0f;
    size_t base = ((size_t)b * SS + ch * 64) * NN + n;
    #pragma unroll 4
    for (int i = 0; i < 64; i++) {
        float av = g_a[base + (size_t)i * NN];
        float bv = g_b[base + (size_t)i * NN];
        A *= av;
        h = fmaf(av, h, bv);
    }
    g_Ac[(b*16 + n)*32 + ch] = A;
    g_Bc[(b*16 + n)*32 + ch] = h;
}
__global__ __launch_bounds__(256) void scan2_kernel()
{
    extern __shared__ float s2[];
    float* sA = s2;
    float* sB = s2 + 256*33;
    const int tid = threadIdx.x;
    #pragma unroll
    for (int i = 0; i < 32; i++) {
        int idx = i * 256 + tid;
        int chain = idx >> 5, c = idx & 31;
        sA[chain*33 + c] = g_Ac[idx];
        sB[chain*33 + c] = g_Bc[idx];
    }
    __syncthreads();
    float carry = 0.0f;
    #pragma unroll
    for (int c = 0; c < 32; c++) {
        g_carry[tid*32 + c] = carry;
        carry = fmaf(sA[tid*33 + c], carry, sB[tid*33 + c]);
    }
}
__global__ __launch_bounds__(256) void scan3_kernel()
{
    int id = blockIdx.x * 256 + threadIdx.x;
    int n = id & 15, ch = (id >> 4) & 31, b = id >> 9;
    float h = g_carry[(b*16 + n)*32 + ch];
    size_t base = ((size_t)b * SS + ch * 64) * NN + n;
    #pragma unroll 4
    for (int i = 0; i < 64; i++) {
        size_t idx = base + (size_t)i * NN;
        h = fmaf(g_a[idx], h, g_b[idx]);
        __half hh = __float2half_rn(h);
        g_hhi[idx] = hh;
        g_hlo[idx] = __float2half_rn(h - __half2float(hh));
    }
}

// ---------------------------------------------------------------------------
// Main: CTA 128x256 (tokens x W-rows), 512 thr, grid (8, 256).
// Per k-chunk (BK=64): load Ahi, Alo, W once; two MMA passes share b-frags.
// Epilogue: y = hs@WC^T via HMMA (K=16, 3-term), then gating fuse.
// ---------------------------------------------------------------------------
#define STG      65536               // Ahi 16K | Alo 16K | W 32K
#define SA_LO    16384
#define SW       32768
#define CS1_OFF  0                   // [128][264] f32 = 135168
#define CS2_OFF  135168              // [128][136] f32 = 69632
#define HT_OFF   204800              // hhi|hlo|wchi|wclo 4x4096
#define BG_OFF   221184
#define BD_OFF   221696
#define SMEM_BYTES 222208
#define NCH 16

__device__ __forceinline__ void load_chunk(uint32_t sb, int c, int m0, int jw, int tid)
{
    int kc = c * 64;
    uint32_t buf = sb + (c & 1) * STG;
    #pragma unroll
    for (int i = 0; i < 8; i++) {
        int u = tid + i * 512;
        int region = u >> 10;         // 0 Ahi, 1 Alo, 2-3 W
        if (region < 2) {
            int v = u & 1023;
            int row = v >> 3, c16 = v & 7;
            const __half* src = (region == 0 ? g_xhi : g_xlo)
                              + (size_t)(m0 + row) * DD + kc + c16 * 8;
            cp16(buf + region * 16384 + row * 128 + ((c16 ^ (row & 7)) << 4), src);
        } else {
            int v = u - 2048;
            int row = v >> 3, c16 = v & 7;
            cp16(buf + SW + row * 128 + ((c16 ^ (row & 7)) << 4),
                 g_whi + (size_t)(jw + row) * DD + kc + c16 * 8);
        }
    }
    CP_COMMIT();
}

__global__ __launch_bounds__(512, 1) void main_kernel(const float* __restrict__ bD,
                                                      const float* __restrict__ bg,
                                                      float* __restrict__ out)
{
    extern __shared__ char smem[];
    uint32_t sb = smem_u32(smem);
    const int tid    = threadIdx.x;
    const int lane   = tid & 31;
    const int wid    = tid >> 5;
    const int warp_m = wid & 1;       // 2 m-groups of 64 rows
    const int warp_n = wid >> 1;      // 8 n-groups of 32 cols
    const int j  = blockIdx.x;        // 0..7
    const int m0 = blockIdx.y * 128;
    const int jw = j * 256;           // W row base
    const uint32_t lh = lane & 7;

    float* BG = (float*)(smem + BG_OFF);
    float* BDs = (float*)(smem + BD_OFF);
    if (tid < 128)      BG[tid] = bg[j*128 + tid];
    else if (tid < 256) BDs[tid-128] = bD[j*128 + tid - 128];

    // HT tiles: hhi|hlo (128x16) and wchi|wclo (128x16) -> 1024 cp16
    #pragma unroll
    for (int i = 0; i < 2; i++) {
        int u = tid + i * 512;
        int region = u >> 8, v = u & 255;
        int row = v >> 1, c16 = v & 1;
        const __half* src;
        if      (region == 0) src = g_hhi  + (size_t)(m0 + row) * NN + c16 * 8;
        else if (region == 1) src = g_hlo  + (size_t)(m0 + row) * NN + c16 * 8;
        else if (region == 2) src = g_wchi + (size_t)(j*128 + row) * NN + c16 * 8;
        else                  src = g_wclo + (size_t)(j*128 + row) * NN + c16 * 8;
        cp16(sb + HT_OFF + region * 4096 + row * 32 + c16 * 16, src);
    }
    load_chunk(sb, 0, m0, jw, tid);   // group 0 (includes HT)

    float d[4][4][4] = {};

    const uint32_t aBase = (uint32_t)((warp_m*64 + (lane & 15)) * 128);
    const uint32_t aHalf = (uint32_t)(lane >> 4);
    const uint32_t bBase = (uint32_t)(SW + (warp_n*32 + ((lane >> 4) << 3) + lh) * 128);
    const uint32_t bHalf = (uint32_t)((lane >> 3) & 1);

    for (int c = 0; c < NCH; c++) {
        __syncthreads();
        if (c + 1 < NCH) { load_chunk(sb, c + 1, m0, jw, tid); CP_WAIT1(); }
        else             CP_WAIT0();
        __syncthreads();

        uint32_t buf = sb + (c & 1) * STG;
        #pragma unroll
        for (int kk = 0; kk < 4; kk++) {
            uint32_t aSw = (((uint32_t)(kk*2) + aHalf) ^ lh) << 4;
            uint32_t bSw = (((uint32_t)(kk*2) + bHalf) ^ lh) << 4;
            uint32_t b[8];
            ldsm4(&b[0], buf + bBase + bSw);
            ldsm4(&b[4], buf + bBase + 2048 + bSw);
            #pragma unroll
            for (int p = 0; p < 2; p++) {
                uint32_t a[4][4];
                #pragma unroll
                for (int mi = 0; mi < 4; mi++)
                    ldsm4(a[mi], buf + p * SA_LO + aBase + mi * 2048 + aSw);
                #pragma unroll
                for (int mi = 0; mi < 4; mi++)
                    #pragma unroll
                    for (int ni = 0; ni < 4; ni++)
                        mma16816(d[mi][ni], a[mi], &b[ni*2]);
            }
        }
    }
    __syncthreads();   // all warps done with stages before overlaying CS1

    // store gate/skip accs -> CS1 [128][264]
    float* CS1 = (float*)(smem + CS1_OFF);
    #pragma unroll
    for (int mi = 0; mi < 4; mi++) {
        #pragma unroll
        for (int ni = 0; ni < 4; ni++) {
            int row0 = warp_m*64 + mi*16 + (lane >> 2);
            int col  = warp_n*32 + ni*8  + (lane & 3) * 2;
            *(float2*)&CS1[row0*264 + col]     = make_float2(d[mi][ni][0], d[mi][ni][1]);
            *(float2*)&CS1[(row0+8)*264 + col] = make_float2(d[mi][ni][2], d[mi][ni][3]);
        }
    }

    // y GEMM: [128 t] x [128 e], K=16, 3-term fp16. Warp tile 64 x 16.
    // B frag order fix: lanes 0-7 -> n0-7/k0-7, 8-15 -> n0-7/k8-15,
    //                   16-23 -> n8-15/k0-7, 24-31 -> n8-15/k8-15.
    {
        float ya[4][2][4] = {};
        uint32_t aO = sb + HT_OFF + (uint32_t)((warp_m*64 + (lane & 15)) * 32 + (lane >> 4) * 16);
        uint32_t bO = sb + HT_OFF + 8192 +
                      (uint32_t)((warp_n*16 + ((lane >> 4) << 3) + lh) * 32 +
                                 ((lane >> 3) & 1) * 16);
        uint32_t ah[4][4], al[4][4], bh[4], bl[4];
        #pragma unroll
        for (int mi = 0; mi < 4; mi++) {
            ldsm4(ah[mi], aO + mi * 512);           // 16 rows * 32B
            ldsm4(al[mi], aO + 4096 + mi * 512);
        }
        ldsm4(bh, bO);
        ldsm4(bl, bO + 4096);
        #pragma unroll
        for (int mi = 0; mi < 4; mi++)
            #pragma unroll
            for (int nj = 0; nj < 2; nj++) {
                mma16816(ya[mi][nj], ah[mi], &bh[nj*2]);
                mma16816(ya[mi][nj], ah[mi], &bl[nj*2]);
                mma16816(ya[mi][nj], al[mi], &bh[nj*2]);
            }
        float* CS2 = (float*)(smem + CS2_OFF);
        #pragma unroll
        for (int mi = 0; mi < 4; mi++)
            #pragma unroll
            for (int nj = 0; nj < 2; nj++) {
                int row0 = warp_m*64 + mi*16 + (lane >> 2);
                int col  = warp_n*16 + nj*8  + (lane & 3) * 2;
                *(float2*)&CS2[row0*136 + col]     = make_float2(ya[mi][nj][0], ya[mi][nj][1]);
                *(float2*)&CS2[(row0+8)*136 + col] = make_float2(ya[mi][nj][2], ya[mi][nj][3]);
            }
    }
    __syncthreads();

    // final gating pass: 16384 outputs
    float* CS1r = (float*)(smem + CS1_OFF);
    float* CS2r = (float*)(smem + CS2_OFF);
    #pragma unroll 4
    for (int it = 0; it < 32; it++) {
        int idx = it * 512 + tid;
        int t = idx >> 7, s = idx & 127;
        int col_g = ((s >> 6) << 7) + (s & 63);
        float c1 = CS1r[t*264 + col_g]      + BG[s];
        float c2 = CS1r[t*264 + col_g + 64] + BDs[s];
        float y  = CS2r[t*136 + s];
        float gv = 1.0f / (1.0f + __expf(-c1));
        out[(size_t)(m0 + t) * DD + j*128 + s] = y * gv + c2 * (1.0f - gv);
    }
}

// ---------------------------------------------------------------------------
extern "C" void kernel_launch(void* const* d_in, const int* in_sizes, int n_in,
                              void* d_out, int out_size)
{
    const float* x  = (const float*)d_in[0];
    const float* WA = (const float*)d_in[1];
    const float* WB = (const float*)d_in[2];
    const float* WC = (const float*)d_in[3];
    const float* WD = (const float*)d_in[4];
    const float* bD = (const float*)d_in[5];
    const float* Wg = (const float*)d_in[6];
    const float* bg = (const float*)d_in[7];
    float* out = (float*)d_out;

    cudaFuncSetAttribute(main_kernel,
                         cudaFuncAttributeMaxDynamicSharedMemorySize, SMEM_BYTES);
    cudaFuncSetAttribute(prep_kernel,
                         cudaFuncAttributeMaxDynamicSharedMemorySize, PREP_SMEM);
    cudaFuncSetAttribute(scan2_kernel,
                         cudaFuncAttributeMaxDynamicSharedMemorySize, 2*256*33*4);

    wsplit_kernel<<<2048, 256>>>(Wg, WD);
    wprep_kernel<<<192, 256>>>(WA, WB, WC);
    prep_kernel<<<256, 256, PREP_SMEM>>>(x);
    scan1_kernel<<<32, 256>>>();
    scan2_kernel<<<1, 256, 2*256*33*4>>>();
    scan3_kernel<<<32, 256>>>();
    main_kernel<<<dim3(8, 256), 512, SMEM_BYTES>>>(bD, bg, out);
}

// round 8
// speedup vs baseline: 5.8128x; 1.0254x over previous
#include <cuda_runtime.h>
#include <cuda_fp16.h>
#include <math.h>
#include <stdint.h>

#define BB 16
#define SS 2048
#define DD 1024
#define NN 16
#define M_TOT (BB*SS)   // 32768 tokens

// ---------------- scratch (__device__ globals) ------------------------------
__device__ __align__(256) float g_a[M_TOT*NN];
__device__ __align__(256) float g_b[M_TOT*NN];
__device__ __align__(256) __half g_hhi[M_TOT*NN];
__device__ __align__(256) __half g_hlo[M_TOT*NN];
__device__ __align__(256) __half g_xhi[(size_t)M_TOT*DD];
__device__ __align__(256) __half g_xlo[(size_t)M_TOT*DD];
__device__ __align__(256) __half g_whi[2048*DD];
__device__ __align__(256) __half g_wabhi[32*DD];
__device__ __align__(256) __half g_wablo[32*DD];
__device__ __align__(256) __half g_wchi[DD*NN];
__device__ __align__(256) __half g_wclo[DD*NN];
__device__ float g_Ac[256*32];
__device__ float g_Bc[256*32];
__device__ float g_carry[256*32];

// ---------------- PTX helpers ----------------------------------------------
__device__ __forceinline__ uint32_t smem_u32(const void* p) {
    uint32_t a;
    asm("{ .reg .u64 t; cvta.to.shared.u64 t, %1; cvt.u32.u64 %0, t; }" : "=r"(a) : "l"(p));
    return a;
}
__device__ __forceinline__ void cp16(uint32_t dst, const void* src) {
    asm volatile("cp.async.cg.shared.global [%0], [%1], 16;" :: "r"(dst), "l"(src) : "memory");
}
#define CP_COMMIT() asm volatile("cp.async.commit_group;" ::: "memory")
#define CP_WAIT1()  asm volatile("cp.async.wait_group 1;" ::: "memory")
#define CP_WAIT0()  asm volatile("cp.async.wait_group 0;" ::: "memory")

__device__ __forceinline__ void ldsm4(uint32_t* r, uint32_t addr) {
    asm volatile("ldmatrix.sync.aligned.m8n8.x4.shared.b16 {%0,%1,%2,%3}, [%4];"
                 : "=r"(r[0]), "=r"(r[1]), "=r"(r[2]), "=r"(r[3]) : "r"(addr));
}
__device__ __forceinline__ void mma16816(float* d, const uint32_t* a, const uint32_t* b) {
    asm volatile("mma.sync.aligned.m16n8k16.row.col.f32.f16.f16.f32 "
                 "{%0,%1,%2,%3}, {%4,%5,%6,%7}, {%8,%9}, {%0,%1,%2,%3};"
                 : "+f"(d[0]), "+f"(d[1]), "+f"(d[2]), "+f"(d[3])
                 : "r"(a[0]), "r"(a[1]), "r"(a[2]), "r"(a[3]), "r"(b[0]), "r"(b[1]));
}

// ---------------------------------------------------------------------------
// wsplit: W rows pair-interleaved at 8-col granularity:
// r = j*256 + p*16 + s : s<8 -> Wg row (j*128 + p*8 + s), s>=8 -> WD same e.
// ---------------------------------------------------------------------------
__global__ __launch_bounds__(256) void wsplit_kernel(const float* __restrict__ Wg,
                                                     const float* __restrict__ WD)
{
    int idx = blockIdx.x * 256 + threadIdx.x;     // 2048 rows * 256 float4
    int r  = idx >> 8;
    int c4 = idx & 255;
    int j = r >> 8, q = r & 255;
    int p = q >> 4, s = q & 15;
    int e = j*128 + p*8 + (s & 7);
    const float* src = (s < 8) ? (Wg + (size_t)e * DD) : (WD + (size_t)e * DD);
    float4 v = ((const float4*)src)[c4];
    __half2 hA = __floats2half2_rn(v.x, v.y);
    __half2 hB = __floats2half2_rn(v.z, v.w);
    uint2 hp;
    hp.x = *(uint32_t*)&hA; hp.y = *(uint32_t*)&hB;
    *(uint2*)(g_whi + (size_t)r * DD + c4 * 4) = hp;
}

// ---------------------------------------------------------------------------
// wprep: WA/WB hi/lo (32x1024) and WC hi/lo (1024x16)
// ---------------------------------------------------------------------------
__global__ __launch_bounds__(256) void wprep_kernel(const float* __restrict__ WA,
                                                    const float* __restrict__ WB,
                                                    const float* __restrict__ WC)
{
    int id = blockIdx.x * 256 + threadIdx.x;      // 192 blocks -> 49152
    float v;
    if (id < 32768) {
        int r = id >> 10, c = id & 1023;
        v = (r < 16) ? WA[(size_t)r * DD + c] : WB[(size_t)(r - 16) * DD + c];
        __half h = __float2half_rn(v);
        g_wabhi[id] = h;
        g_wablo[id] = __float2half_rn(v - __half2float(h));
    } else {
        int i2 = id - 32768;                      // WC: 1024*16
        v = WC[i2];
        __half h = __float2half_rn(v);
        g_wchi[i2] = h;
        g_wclo[i2] = __float2half_rn(v - __half2float(h));
    }
}

// ---------------------------------------------------------------------------
// prep: read x once -> write xhi/xlo; compute a=tanh(x@WA^T), b=x@WB^T via
// 3-term fp16 HMMA.
// ---------------------------------------------------------------------------
#define PXF 0
#define PXH 34816
#define PXL 51200
#define PWH 67584
#define PWL 71680
#define PREP_SMEM 75776

__global__ __launch_bounds__(256) void prep_kernel(const float* __restrict__ x)
{
    extern __shared__ char smem[];
    uint32_t sb = smem_u32(smem);
    const int tid  = threadIdx.x;
    const int lane = tid & 31;
    const int wid  = tid >> 5;
    const int m0   = blockIdx.x * 128;
    const uint32_t lh = lane & 7;

    float acc[4][4] = {};

    for (int c = 0; c < 16; c++) {
        int kc = c * 64;
        #pragma unroll
        for (int i = 0; i < 8; i++) {
            int u = tid + i * 256;
            int row = u >> 4, c4 = u & 15;
            cp16(sb + PXF + row * 272 + c4 * 16,
                 x + (size_t)(m0 + row) * DD + kc + c4 * 4);
        }
        #pragma unroll
        for (int i = 0; i < 2; i++) {
            int u = tid + i * 256;
            int sel = u >> 8, v = u & 255;
            int row = v >> 3, c16 = v & 7;
            const __half* src = (sel == 0 ? g_wabhi : g_wablo) + (size_t)row * DD + kc + c16 * 8;
            cp16(sb + (sel == 0 ? PWH : PWL) + row * 128 + ((c16 ^ (row & 7)) << 4), src);
        }
        CP_COMMIT();
        CP_WAIT0();
        __syncthreads();

        #pragma unroll
        for (int i = 0; i < 8; i++) {
            int u = tid + i * 256;
            int row = u >> 4;
            int q   = u & 15;
            float4 v = *(const float4*)(smem + PXF + row * 272 + q * 16);
            __half hx = __float2half_rn(v.x), hy = __float2half_rn(v.y);
            __half hz = __float2half_rn(v.z), hw = __float2half_rn(v.w);
            __half2 hA = __halves2half2(hx, hy), hB = __halves2half2(hz, hw);
            __half2 lA = __floats2half2_rn(v.x - __half2float(hx), v.y - __half2float(hy));
            __half2 lB = __floats2half2_rn(v.z - __half2float(hz), v.w - __half2float(hw));
            uint2 hp, lp;
            hp.x = *(uint32_t*)&hA; hp.y = *(uint32_t*)&hB;
            lp.x = *(uint32_t*)&lA; lp.y = *(uint32_t*)&lB;
            int c16 = q >> 1;
            uint32_t soff = row * 128 + (((uint32_t)c16 ^ (row & 7)) << 4) + (q & 1) * 8;
            *(uint2*)(smem + PXH + soff) = hp;
            *(uint2*)(smem + PXL + soff) = lp;
            size_t goff = (size_t)(m0 + row) * DD + kc + q * 4;
            *(uint2*)(g_xhi + goff) = hp;
            *(uint2*)(g_xlo + goff) = lp;
        }
        __syncthreads();

        const uint32_t aBase = (uint32_t)((wid * 16 + (lane & 15)) * 128);
        const uint32_t bRow  = (uint32_t)(((lane >> 4) << 3) + lh);
        #pragma unroll
        for (int kk = 0; kk < 4; kk++) {
            uint32_t aSw = (((uint32_t)(kk*2) + (lane >> 4)) ^ lh) << 4;
            uint32_t bSw = (((uint32_t)(kk*2) + ((lane >> 3) & 1)) ^ lh) << 4;
            uint32_t ah[4], al[4], bh[8], bl[8];
            ldsm4(ah, sb + PXH + aBase + aSw);
            ldsm4(al, sb + PXL + aBase + aSw);
            ldsm4(&bh[0], sb + PWH + bRow * 128 + bSw);
            ldsm4(&bh[4], sb + PWH + (bRow + 16) * 128 + bSw);
            ldsm4(&bl[0], sb + PWL + bRow * 128 + bSw);
            ldsm4(&bl[4], sb + PWL + (bRow + 16) * 128 + bSw);
            #pragma unroll
            for (int ni = 0; ni < 4; ni++) {
                mma16816(acc[ni], ah, &bh[ni*2]);
                mma16816(acc[ni], ah, &bl[ni*2]);
                mma16816(acc[ni], al, &bh[ni*2]);
            }
        }
        __syncthreads();
    }

    #pragma unroll
    for (int ni = 0; ni < 4; ni++) {
        #pragma unroll
        for (int fr = 0; fr < 4; fr++) {
            int row = m0 + wid*16 + (lane >> 2) + (fr >> 1) * 8;
            int col = ni*8 + (lane & 3) * 2 + (fr & 1);
            float v = acc[ni][fr];
            if (col < 16) g_a[(size_t)row * NN + col]        = tanhf(v);
            else          g_b[(size_t)row * NN + (col - 16)] = v;
        }
    }
}

// ---------------------------------------------------------------------------
// Chunked parallel scan; scan3 emits fp16 hi/lo of h
// ---------------------------------------------------------------------------
__global__ __launch_bounds__(256) void scan1_kernel()
{
    int id = blockIdx.x * 256 + threadIdx.x;
    int n = id & 15, ch = (id >> 4) & 31, b = id >> 9;
    float A = 1.0f, h = 0.0f;
    size_t base = ((size_t)b * SS + ch * 64) * NN + n;
    #pragma unroll 4
    for (int i = 0; i < 64; i++) {
        float av = g_a[base + (size_t)i * NN];
        float bv = g_b[base + (size_t)i * NN];
        A *= av;
        h = fmaf(av, h, bv);
    }
    g_Ac[(b*16 + n)*32 + ch] = A;
    g_Bc[(b*16 + n)*32 + ch] = h;
}
__global__ __launch_bounds__(256) void scan2_kernel()
{
    extern __shared__ float s2[];
    float* sA = s2;
    float* sB = s2 + 256*33;
    const int tid = threadIdx.x;
    #pragma unroll
    for (int i = 0; i < 32; i++) {
        int idx = i * 256 + tid;
        int chain = idx >> 5, c = idx & 31;
        sA[chain*33 + c] = g_Ac[idx];
        sB[chain*33 + c] = g_Bc[idx];
    }
    __syncthreads();
    float carry = 0.0f;
    #pragma unroll
    for (int c = 0; c < 32; c++) {
        g_carry[tid*32 + c] = carry;
        carry = fmaf(sA[tid*33 + c], carry, sB[tid*33 + c]);
    }
}
__global__ __launch_bounds__(256) void scan3_kernel()
{
    int id = blockIdx.x * 256 + threadIdx.x;
    int n = id & 15, ch = (id >> 4) & 31, b = id >> 9;
    float h = g_carry[(b*16 + n)*32 + ch];
    size_t base = ((size_t)b * SS + ch * 64) * NN + n;
    #pragma unroll 4
    for (int i = 0; i < 64; i++) {
        size_t idx = base + (size_t)i * NN;
        h = fmaf(g_a[idx], h, g_b[idx]);
        __half hh = __float2half_rn(h);
        g_hhi[idx] = hh;
        g_hlo[idx] = __float2half_rn(h - __half2float(hh));
    }
}

// ---------------------------------------------------------------------------
// Main: CTA 128x256, 512 thr, grid (8, 256). 3-stage ring, 1 sync/chunk.
// Gate/skip pair-interleaved in W -> epilogue (y-GEMM + gating) in registers.
// ---------------------------------------------------------------------------
#define STG      65536               // Ahi 16K | Alo 16K | W 32K
#define SA_LO    16384
#define SW       32768
#define HT_OFF   (3*STG)             // hhi|hlo|wchi|wclo 4x4096
#define SMEM_BYTES (HT_OFF + 16384)  // 212992
#define NCH 16

__device__ __forceinline__ void load_chunk(uint32_t sb, int c, int m0, int jw, int tid)
{
    int kc = c * 64;
    uint32_t buf = sb + (uint32_t)(c % 3) * STG;
    #pragma unroll
    for (int i = 0; i < 8; i++) {
        int u = tid + i * 512;
        int region = u >> 10;         // 0 Ahi, 1 Alo, 2-3 W
        if (region < 2) {
            int v = u & 1023;
            int row = v >> 3, c16 = v & 7;
            const __half* src = (region == 0 ? g_xhi : g_xlo)
                              + (size_t)(m0 + row) * DD + kc + c16 * 8;
            cp16(buf + region * 16384 + row * 128 + ((c16 ^ (row & 7)) << 4), src);
        } else {
            int v = u - 2048;
            int row = v >> 3, c16 = v & 7;
            cp16(buf + SW + row * 128 + ((c16 ^ (row & 7)) << 4),
                 g_whi + (size_t)(jw + row) * DD + kc + c16 * 8);
        }
    }
    CP_COMMIT();
}

__global__ __launch_bounds__(512) void main_kernel(const float* __restrict__ bD,
                                                   const float* __restrict__ bg,
                                                   float* __restrict__ out)
{
    extern __shared__ char smem[];
    uint32_t sb = smem_u32(smem);
    const int tid    = threadIdx.x;
    const int lane   = tid & 31;
    const int wid    = tid >> 5;
    const int warp_m = wid & 1;       // 2 m-groups of 64 rows
    const int warp_n = wid >> 1;      // 8 n-groups of 32 cols
    const int j  = blockIdx.x;        // 0..7
    const int m0 = blockIdx.y * 128;
    const int jw = j * 256;
    const uint32_t lh = lane & 7;

    // HT tiles: hhi|hlo (128x16), wchi|wclo (128x16) -> 1024 cp16
    #pragma unroll
    for (int i = 0; i < 2; i++) {
        int u = tid + i * 512;
        int region = u >> 8, v = u & 255;
        int row = v >> 1, c16 = v & 1;
        const __half* src;
        if      (region == 0) src = g_hhi  + (size_t)(m0 + row) * NN + c16 * 8;
        else if (region == 1) src = g_hlo  + (size_t)(m0 + row) * NN + c16 * 8;
        else if (region == 2) src = g_wchi + (size_t)(j*128 + row) * NN + c16 * 8;
        else                  src = g_wclo + (size_t)(j*128 + row) * NN + c16 * 8;
        cp16(sb + HT_OFF + region * 4096 + row * 32 + c16 * 16, src);
    }
    load_chunk(sb, 0, m0, jw, tid);   // group 0 (includes HT)
    load_chunk(sb, 1, m0, jw, tid);   // group 1

    float d[4][4][4] = {};

    const uint32_t aBase = (uint32_t)((warp_m*64 + (lane & 15)) * 128);
    const uint32_t aHalf = (uint32_t)(lane >> 4);
    const uint32_t bBase = (uint32_t)(SW + (warp_n*32 + ((lane >> 4) << 3) + lh) * 128);
    const uint32_t bHalf = (uint32_t)((lane >> 3) & 1);

    for (int c = 0; c < NCH; c++) {
        if (c == NCH - 1) CP_WAIT0(); else CP_WAIT1();
        __syncthreads();
        if (c + 2 < NCH) load_chunk(sb, c + 2, m0, jw, tid);

        uint32_t buf = sb + (uint32_t)(c % 3) * STG;
        #pragma unroll
        for (int kk = 0; kk < 4; kk++) {
            uint32_t aSw = (((uint32_t)(kk*2) + aHalf) ^ lh) << 4;
            uint32_t bSw = (((uint32_t)(kk*2) + bHalf) ^ lh) << 4;
            uint32_t b[8];
            ldsm4(&b[0], buf + bBase + bSw);
            ldsm4(&b[4], buf + bBase + 2048 + bSw);
            #pragma unroll
            for (int p = 0; p < 2; p++) {
                uint32_t a[4][4];
                #pragma unroll
                for (int mi = 0; mi < 4; mi++)
                    ldsm4(a[mi], buf + p * SA_LO + aBase + mi * 2048 + aSw);
                #pragma unroll
                for (int mi = 0; mi < 4; mi++)
                    #pragma unroll
                    for (int ni = 0; ni < 4; ni++)
                        mma16816(d[mi][ni], a[mi], &b[ni*2]);
            }
        }
    }

    // ---- register epilogue: y = hs@WC^T (3-term fp16), then gating ----
    // (d[mi][2*nj] = gate acc, d[mi][2*nj+1] = skip acc at SAME coords as ya)
    uint32_t bh[4], bl[4];
    const uint32_t bO = sb + HT_OFF + 8192 +
        (uint32_t)((warp_n*16 + ((lane >> 4) << 3) + lh) * 32 + ((lane >> 3) & 1) * 16);
    ldsm4(bh, bO);
    ldsm4(bl, bO + 4096);
    const uint32_t aO = sb + HT_OFF +
        (uint32_t)((warp_m*64 + (lane & 15)) * 32 + (lane >> 4) * 16);

    const int ecol = j*128 + warp_n*16 + (lane & 3) * 2;
    const float2 bg0 = *(const float2*)(bg + ecol);
    const float2 bg1 = *(const float2*)(bg + ecol + 8);
    const float2 bd0 = *(const float2*)(bD + ecol);
    const float2 bd1 = *(const float2*)(bD + ecol + 8);

    #pragma unroll
    for (int mi = 0; mi < 4; mi++) {
        uint32_t ah[4], al[4];
        ldsm4(ah, aO + mi * 512);
        ldsm4(al, aO + 4096 + mi * 512);
        float ya[2][4] = {};
        #pragma unroll
        for (int nj = 0; nj < 2; nj++) {
            mma16816(ya[nj], ah, &bh[nj*2]);
            mma16816(ya[nj], ah, &bl[nj*2]);
            mma16816(ya[nj], al, &bh[nj*2]);
        }
        #pragma unroll
        for (int nj = 0; nj < 2; nj++) {
            float2 bgv = nj ? bg1 : bg0;
            float2 bdv = nj ? bd1 : bd0;
            #pragma unroll
            for (int hl = 0; hl < 2; hl++) {
                int row = m0 + warp_m*64 + mi*16 + (lane >> 2) + hl*8;
                float g0 = 1.0f / (1.0f + __expf(-(d[mi][2*nj][hl*2+0] + bgv.x)));
                float g1 = 1.0f / (1.0f + __expf(-(d[mi][2*nj][hl*2+1] + bgv.y)));
                float x0 = d[mi][2*nj+1][hl*2+0] + bdv.x;
                float x1 = d[mi][2*nj+1][hl*2+1] + bdv.y;
                float2 o;
                o.x = ya[nj][hl*2+0] * g0 + x0 * (1.0f - g0);
                o.y = ya[nj][hl*2+1] * g1 + x1 * (1.0f - g1);
                *(float2*)(out + (size_t)row * DD + ecol + nj*8) = o;
            }
        }
    }
}

// ---------------------------------------------------------------------------
extern "C" void kernel_launch(void* const* d_in, const int* in_sizes, int n_in,
                              void* d_out, int out_size)
{
    const float* x  = (const float*)d_in[0];
    const float* WA = (const float*)d_in[1];
    const float* WB = (const float*)d_in[2];
    const float* WC = (const float*)d_in[3];
    const float* WD = (const float*)d_in[4];
    const float* bD = (const float*)d_in[5];
    const float* Wg = (const float*)d_in[6];
    const float* bg = (const float*)d_in[7];
    float* out = (float*)d_out;

    cudaFuncSetAttribute(main_kernel,
                         cudaFuncAttributeMaxDynamicSharedMemorySize, SMEM_BYTES);
    cudaFuncSetAttribute(prep_kernel,
                         cudaFuncAttributeMaxDynamicSharedMemorySize, PREP_SMEM);
    cudaFuncSetAttribute(scan2_kernel,
                         cudaFuncAttributeMaxDynamicSharedMemorySize, 2*256*33*4);

    wsplit_kernel<<<2048, 256>>>(Wg, WD);
    wprep_kernel<<<192, 256>>>(WA, WB, WC);
    prep_kernel<<<256, 256, PREP_SMEM>>>(x);
    scan1_kernel<<<32, 256>>>();
    scan2_kernel<<<1, 256, 2*256*33*4>>>();
    scan3_kernel<<<32, 256>>>();
    main_kernel<<<dim3(8, 256), 512, SMEM_BYTES>>>(bD, bg, out);
}

// round 9
// speedup vs baseline: 9.2943x; 1.5989x over previous
#include <cuda_runtime.h>
#include <cuda_fp16.h>
#include <math.h>
#include <stdint.h>

#define BB 16
#define SS 2048
#define DD 1024
#define NN 16
#define M_TOT (BB*SS)   // 32768 tokens

// ---------------- scratch (__device__ globals) ------------------------------
__device__ __align__(256) float g_a[M_TOT*NN];
__device__ __align__(256) float g_b[M_TOT*NN];
__device__ __align__(256) __half g_hhi[M_TOT*NN];
__device__ __align__(256) __half g_hlo[M_TOT*NN];
__device__ __align__(256) __half g_xhi[(size_t)M_TOT*DD];
__device__ __align__(256) __half g_whi[2048*DD];
__device__ __align__(256) __half g_wabhi[32*DD];
__device__ __align__(256) __half g_wablo[32*DD];
__device__ __align__(256) __half g_wchi[DD*NN];
__device__ __align__(256) __half g_wclo[DD*NN];
__device__ float g_Ac[256*32];
__device__ float g_Bc[256*32];
__device__ float g_carry[256*32];

// ---------------- PTX helpers ----------------------------------------------
__device__ __forceinline__ uint32_t smem_u32(const void* p) {
    uint32_t a;
    asm("{ .reg .u64 t; cvta.to.shared.u64 t, %1; cvt.u32.u64 %0, t; }" : "=r"(a) : "l"(p));
    return a;
}
__device__ __forceinline__ void cp16(uint32_t dst, const void* src) {
    asm volatile("cp.async.cg.shared.global [%0], [%1], 16;" :: "r"(dst), "l"(src) : "memory");
}
#define CP_COMMIT() asm volatile("cp.async.commit_group;" ::: "memory")
#define CP_WAIT2()  asm volatile("cp.async.wait_group 2;" ::: "memory")
#define CP_WAIT1()  asm volatile("cp.async.wait_group 1;" ::: "memory")
#define CP_WAIT0()  asm volatile("cp.async.wait_group 0;" ::: "memory")

__device__ __forceinline__ void ldsm4(uint32_t* r, uint32_t addr) {
    asm volatile("ldmatrix.sync.aligned.m8n8.x4.shared.b16 {%0,%1,%2,%3}, [%4];"
                 : "=r"(r[0]), "=r"(r[1]), "=r"(r[2]), "=r"(r[3]) : "r"(addr));
}
__device__ __forceinline__ void mma16816(float* d, const uint32_t* a, const uint32_t* b) {
    asm volatile("mma.sync.aligned.m16n8k16.row.col.f32.f16.f16.f32 "
                 "{%0,%1,%2,%3}, {%4,%5,%6,%7}, {%8,%9}, {%0,%1,%2,%3};"
                 : "+f"(d[0]), "+f"(d[1]), "+f"(d[2]), "+f"(d[3])
                 : "r"(a[0]), "r"(a[1]), "r"(a[2]), "r"(a[3]), "r"(b[0]), "r"(b[1]));
}

// ---------------------------------------------------------------------------
// wsplit: W rows pair-interleaved at 8-col granularity:
// r = j*256 + p*16 + s : s<8 -> Wg row (j*128 + p*8 + s), s>=8 -> WD same e.
// ---------------------------------------------------------------------------
__global__ __launch_bounds__(256) void wsplit_kernel(const float* __restrict__ Wg,
                                                     const float* __restrict__ WD)
{
    int idx = blockIdx.x * 256 + threadIdx.x;     // 2048 rows * 256 float4
    int r  = idx >> 8;
    int c4 = idx & 255;
    int j = r >> 8, q = r & 255;
    int p = q >> 4, s = q & 15;
    int e = j*128 + p*8 + (s & 7);
    const float* src = (s < 8) ? (Wg + (size_t)e * DD) : (WD + (size_t)e * DD);
    float4 v = ((const float4*)src)[c4];
    __half2 hA = __floats2half2_rn(v.x, v.y);
    __half2 hB = __floats2half2_rn(v.z, v.w);
    uint2 hp;
    hp.x = *(uint32_t*)&hA; hp.y = *(uint32_t*)&hB;
    *(uint2*)(g_whi + (size_t)r * DD + c4 * 4) = hp;
}

// ---------------------------------------------------------------------------
// wprep: WA/WB hi/lo (32x1024) and WC hi/lo (1024x16)
// ---------------------------------------------------------------------------
__global__ __launch_bounds__(256) void wprep_kernel(const float* __restrict__ WA,
                                                    const float* __restrict__ WB,
                                                    const float* __restrict__ WC)
{
    int id = blockIdx.x * 256 + threadIdx.x;      // 192 blocks -> 49152
    float v;
    if (id < 32768) {
        int r = id >> 10, c = id & 1023;
        v = (r < 16) ? WA[(size_t)r * DD + c] : WB[(size_t)(r - 16) * DD + c];
        __half h = __float2half_rn(v);
        g_wabhi[id] = h;
        g_wablo[id] = __float2half_rn(v - __half2float(h));
    } else {
        int i2 = id - 32768;                      // WC: 1024*16
        v = WC[i2];
        __half h = __float2half_rn(v);
        g_wchi[i2] = h;
        g_wclo[i2] = __float2half_rn(v - __half2float(h));
    }
}

// ---------------------------------------------------------------------------
// prep: read x once -> write xhi; compute a=tanh(x@WA^T), b=x@WB^T via
// 3-term fp16 HMMA (keeps scan inputs accurate; xlo lives only in smem).
// ---------------------------------------------------------------------------
#define PXF 0
#define PXH 34816
#define PXL 51200
#define PWH 67584
#define PWL 71680
#define PREP_SMEM 75776

__global__ __launch_bounds__(256) void prep_kernel(const float* __restrict__ x)
{
    extern __shared__ char smem[];
    uint32_t sb = smem_u32(smem);
    const int tid  = threadIdx.x;
    const int lane = tid & 31;
    const int wid  = tid >> 5;
    const int m0   = blockIdx.x * 128;
    const uint32_t lh = lane & 7;

    float acc[4][4] = {};

    for (int c = 0; c < 16; c++) {
        int kc = c * 64;
        #pragma unroll
        for (int i = 0; i < 8; i++) {
            int u = tid + i * 256;
            int row = u >> 4, c4 = u & 15;
            cp16(sb + PXF + row * 272 + c4 * 16,
                 x + (size_t)(m0 + row) * DD + kc + c4 * 4);
        }
        #pragma unroll
        for (int i = 0; i < 2; i++) {
            int u = tid + i * 256;
            int sel = u >> 8, v = u & 255;
            int row = v >> 3, c16 = v & 7;
            const __half* src = (sel == 0 ? g_wabhi : g_wablo) + (size_t)row * DD + kc + c16 * 8;
            cp16(sb + (sel == 0 ? PWH : PWL) + row * 128 + ((c16 ^ (row & 7)) << 4), src);
        }
        CP_COMMIT();
        CP_WAIT0();
        __syncthreads();

        #pragma unroll
        for (int i = 0; i < 8; i++) {
            int u = tid + i * 256;
            int row = u >> 4;
            int q   = u & 15;
            float4 v = *(const float4*)(smem + PXF + row * 272 + q * 16);
            __half hx = __float2half_rn(v.x), hy = __float2half_rn(v.y);
            __half hz = __float2half_rn(v.z), hw = __float2half_rn(v.w);
            __half2 hA = __halves2half2(hx, hy), hB = __halves2half2(hz, hw);
            __half2 lA = __floats2half2_rn(v.x - __half2float(hx), v.y - __half2float(hy));
            __half2 lB = __floats2half2_rn(v.z - __half2float(hz), v.w - __half2float(hw));
            uint2 hp, lp;
            hp.x = *(uint32_t*)&hA; hp.y = *(uint32_t*)&hB;
            lp.x = *(uint32_t*)&lA; lp.y = *(uint32_t*)&lB;
            int c16 = q >> 1;
            uint32_t soff = row * 128 + (((uint32_t)c16 ^ (row & 7)) << 4) + (q & 1) * 8;
            *(uint2*)(smem + PXH + soff) = hp;
            *(uint2*)(smem + PXL + soff) = lp;
            *(uint2*)(g_xhi + (size_t)(m0 + row) * DD + kc + q * 4) = hp;
        }
        __syncthreads();

        const uint32_t aBase = (uint32_t)((wid * 16 + (lane & 15)) * 128);
        const uint32_t bRow  = (uint32_t)(((lane >> 4) << 3) + lh);
        #pragma unroll
        for (int kk = 0; kk < 4; kk++) {
            uint32_t aSw = (((uint32_t)(kk*2) + (lane >> 4)) ^ lh) << 4;
            uint32_t bSw = (((uint32_t)(kk*2) + ((lane >> 3) & 1)) ^ lh) << 4;
            uint32_t ah[4], al[4], bh[8], bl[8];
            ldsm4(ah, sb + PXH + aBase + aSw);
            ldsm4(al, sb + PXL + aBase + aSw);
            ldsm4(&bh[0], sb + PWH + bRow * 128 + bSw);
            ldsm4(&bh[4], sb + PWH + (bRow + 16) * 128 + bSw);
            ldsm4(&bl[0], sb + PWL + bRow * 128 + bSw);
            ldsm4(&bl[4], sb + PWL + (bRow + 16) * 128 + bSw);
            #pragma unroll
            for (int ni = 0; ni < 4; ni++) {
                mma16816(acc[ni], ah, &bh[ni*2]);
                mma16816(acc[ni], ah, &bl[ni*2]);
                mma16816(acc[ni], al, &bh[ni*2]);
            }
        }
        __syncthreads();
    }

    #pragma unroll
    for (int ni = 0; ni < 4; ni++) {
        #pragma unroll
        for (int fr = 0; fr < 4; fr++) {
            int row = m0 + wid*16 + (lane >> 2) + (fr >> 1) * 8;
            int col = ni*8 + (lane & 3) * 2 + (fr & 1);
            float v = acc[ni][fr];
            if (col < 16) g_a[(size_t)row * NN + col]        = tanhf(v);
            else          g_b[(size_t)row * NN + (col - 16)] = v;
        }
    }
}

// ---------------------------------------------------------------------------
// Chunked parallel scan; scan3 emits fp16 hi/lo of h
// ---------------------------------------------------------------------------
__global__ __launch_bounds__(256) void scan1_kernel()
{
    int id = blockIdx.x * 256 + threadIdx.x;
    int n = id & 15, ch = (id >> 4) & 31, b = id >> 9;
    float A = 1.0f, h = 0.0f;
    size_t base = ((size_t)b * SS + ch * 64) * NN + n;
    #pragma unroll 4
    for (int i = 0; i < 64; i++) {
        float av = g_a[base + (size_t)i * NN];
        float bv = g_b[base + (size_t)i * NN];
        A *= av;
        h = fmaf(av, h, bv);
    }
    g_Ac[(b*16 + n)*32 + ch] = A;
    g_Bc[(b*16 + n)*32 + ch] = h;
}
__global__ __launch_bounds__(256) void scan2_kernel()
{
    extern __shared__ float s2[];
    float* sA = s2;
    float* sB = s2 + 256*33;
    const int tid = threadIdx.x;
    #pragma unroll
    for (int i = 0; i < 32; i++) {
        int idx = i * 256 + tid;
        int chain = idx >> 5, c = idx & 31;
        sA[chain*33 + c] = g_Ac[idx];
        sB[chain*33 + c] = g_Bc[idx];
    }
    __syncthreads();
    float carry = 0.0f;
    #pragma unroll
    for (int c = 0; c < 32; c++) {
        g_carry[tid*32 + c] = carry;
        carry = fmaf(sA[tid*33 + c], carry, sB[tid*33 + c]);
    }
}
__global__ __launch_bounds__(256) void scan3_kernel()
{
    int id = blockIdx.x * 256 + threadIdx.x;
    int n = id & 15, ch = (id >> 4) & 31, b = id >> 9;
    float h = g_carry[(b*16 + n)*32 + ch];
    size_t base = ((size_t)b * SS + ch * 64) * NN + n;
    #pragma unroll 4
    for (int i = 0; i < 64; i++) {
        size_t idx = base + (size_t)i * NN;
        h = fmaf(g_a[idx], h, g_b[idx]);
        __half hh = __float2half_rn(h);
        g_hhi[idx] = hh;
        g_hlo[idx] = __float2half_rn(h - __half2float(hh));
    }
}

// ---------------------------------------------------------------------------
// Main: CTA 128x256, 512 thr, grid (8, 256). Single-term fp16, 4-stage ring,
// 1 sync/chunk. Gate/skip pair-interleaved -> full register epilogue.
// ---------------------------------------------------------------------------
#define STG      49152               // A 16K | W 32K
#define SW       16384
#define HT_OFF   (4*STG)             // 196608: hhi|hlo|wchi|wclo 4x4096
#define SMEM_BYTES (HT_OFF + 16384)  // 212992
#define NCH 16

__device__ __forceinline__ void load_chunk(uint32_t sb, int c, int m0, int jw, int tid)
{
    int kc = c * 64;
    uint32_t buf = sb + (uint32_t)(c & 3) * STG;
    #pragma unroll
    for (int i = 0; i < 6; i++) {
        int u = tid + i * 512;        // 3072 cp16
        if (u < 1024) {               // A: 128 rows x 8 c16
            int row = u >> 3, c16 = u & 7;
            cp16(buf + row * 128 + ((c16 ^ (row & 7)) << 4),
                 g_xhi + (size_t)(m0 + row) * DD + kc + c16 * 8);
        } else {                      // W: 256 rows x 8 c16
            int v = u - 1024;
            int row = v >> 3, c16 = v & 7;
            cp16(buf + SW + row * 128 + ((c16 ^ (row & 7)) << 4),
                 g_whi + (size_t)(jw + row) * DD + kc + c16 * 8);
        }
    }
    CP_COMMIT();
}

__global__ __launch_bounds__(512) void main_kernel(const float* __restrict__ bD,
                                                   const float* __restrict__ bg,
                                                   float* __restrict__ out)
{
    extern __shared__ char smem[];
    uint32_t sb = smem_u32(smem);
    const int tid    = threadIdx.x;
    const int lane   = tid & 31;
    const int wid    = tid >> 5;
    const int warp_m = wid & 1;       // 2 m-groups of 64 rows
    const int warp_n = wid >> 1;      // 8 n-groups of 32 cols
    const int j  = blockIdx.x;        // 0..7
    const int m0 = blockIdx.y * 128;
    const int jw = j * 256;
    const uint32_t lh = lane & 7;

    // HT tiles: hhi|hlo (128x16), wchi|wclo (128x16) -> 1024 cp16
    #pragma unroll
    for (int i = 0; i < 2; i++) {
        int u = tid + i * 512;
        int region = u >> 8, v = u & 255;
        int row = v >> 1, c16 = v & 1;
        const __half* src;
        if      (region == 0) src = g_hhi  + (size_t)(m0 + row) * NN + c16 * 8;
        else if (region == 1) src = g_hlo  + (size_t)(m0 + row) * NN + c16 * 8;
        else if (region == 2) src = g_wchi + (size_t)(j*128 + row) * NN + c16 * 8;
        else                  src = g_wclo + (size_t)(j*128 + row) * NN + c16 * 8;
        cp16(sb + HT_OFF + region * 4096 + row * 32 + c16 * 16, src);
    }
    load_chunk(sb, 0, m0, jw, tid);   // group 0 (includes HT)
    load_chunk(sb, 1, m0, jw, tid);   // group 1
    load_chunk(sb, 2, m0, jw, tid);   // group 2

    float d[4][4][4] = {};

    const uint32_t aBase = (uint32_t)((warp_m*64 + (lane & 15)) * 128);
    const uint32_t aHalf = (uint32_t)(lane >> 4);
    const uint32_t bBase = (uint32_t)(SW + (warp_n*32 + ((lane >> 4) << 3) + lh) * 128);
    const uint32_t bHalf = (uint32_t)((lane >> 3) & 1);

    for (int c = 0; c < NCH; c++) {
        if      (c + 1 == NCH) CP_WAIT0();
        else if (c + 2 == NCH) CP_WAIT1();
        else                   CP_WAIT2();
        __syncthreads();
        if (c + 3 < NCH) load_chunk(sb, c + 3, m0, jw, tid);

        uint32_t buf = sb + (uint32_t)(c & 3) * STG;
        #pragma unroll
        for (int kk = 0; kk < 4; kk++) {
            uint32_t aSw = (((uint32_t)(kk*2) + aHalf) ^ lh) << 4;
            uint32_t bSw = (((uint32_t)(kk*2) + bHalf) ^ lh) << 4;
            uint32_t b[8], a[4][4];
            ldsm4(&b[0], buf + bBase + bSw);
            ldsm4(&b[4], buf + bBase + 2048 + bSw);
            #pragma unroll
            for (int mi = 0; mi < 4; mi++)
                ldsm4(a[mi], buf + aBase + mi * 2048 + aSw);
            #pragma unroll
            for (int mi = 0; mi < 4; mi++)
                #pragma unroll
                for (int ni = 0; ni < 4; ni++)
                    mma16816(d[mi][ni], a[mi], &b[ni*2]);
        }
    }

    // ---- register epilogue: y = hs@WC^T (3-term fp16), then gating ----
    uint32_t bh[4], bl[4];
    const uint32_t bO = sb + HT_OFF + 8192 +
        (uint32_t)((warp_n*16 + ((lane >> 4) << 3) + lh) * 32 + ((lane >> 3) & 1) * 16);
    ldsm4(bh, bO);
    ldsm4(bl, bO + 4096);
    const uint32_t aO = sb + HT_OFF +
        (uint32_t)((warp_m*64 + (lane & 15)) * 32 + (lane >> 4) * 16);

    const int ecol = j*128 + warp_n*16 + (lane & 3) * 2;
    const float2 bg0 = *(const float2*)(bg + ecol);
    const float2 bg1 = *(const float2*)(bg + ecol + 8);
    const float2 bd0 = *(const float2*)(bD + ecol);
    const float2 bd1 = *(const float2*)(bD + ecol + 8);

    #pragma unroll
    for (int mi = 0; mi < 4; mi++) {
        uint32_t ah[4], al[4];
        ldsm4(ah, aO + mi * 512);
        ldsm4(al, aO + 4096 + mi * 512);
        float ya[2][4] = {};
        #pragma unroll
        for (int nj = 0; nj < 2; nj++) {
            mma16816(ya[nj], ah, &bh[nj*2]);
            mma16816(ya[nj], ah, &bl[nj*2]);
            mma16816(ya[nj], al, &bh[nj*2]);
        }
        #pragma unroll
        for (int nj = 0; nj < 2; nj++) {
            float2 bgv = nj ? bg1 : bg0;
            float2 bdv = nj ? bd1 : bd0;
            #pragma unroll
            for (int hl = 0; hl < 2; hl++) {
                int row = m0 + warp_m*64 + mi*16 + (lane >> 2) + hl*8;
                float g0 = 1.0f / (1.0f + __expf(-(d[mi][2*nj][hl*2+0] + bgv.x)));
                float g1 = 1.0f / (1.0f + __expf(-(d[mi][2*nj][hl*2+1] + bgv.y)));
                float x0 = d[mi][2*nj+1][hl*2+0] + bdv.x;
                float x1 = d[mi][2*nj+1][hl*2+1] + bdv.y;
                float2 o;
                o.x = ya[nj][hl*2+0] * g0 + x0 * (1.0f - g0);
                o.y = ya[nj][hl*2+1] * g1 + x1 * (1.0f - g1);
                *(float2*)(out + (size_t)row * DD + ecol + nj*8) = o;
            }
        }
    }
}

// ---------------------------------------------------------------------------
extern "C" void kernel_launch(void* const* d_in, const int* in_sizes, int n_in,
                              void* d_out, int out_size)
{
    const float* x  = (const float*)d_in[0];
    const float* WA = (const float*)d_in[1];
    const float* WB = (const float*)d_in[2];
    const float* WC = (const float*)d_in[3];
    const float* WD = (const float*)d_in[4];
    const float* bD = (const float*)d_in[5];
    const float* Wg = (const float*)d_in[6];
    const float* bg = (const float*)d_in[7];
    float* out = (float*)d_out;

    cudaFuncSetAttribute(main_kernel,
                         cudaFuncAttributeMaxDynamicSharedMemorySize, SMEM_BYTES);
    cudaFuncSetAttribute(prep_kernel,
                         cudaFuncAttributeMaxDynamicSharedMemorySize, PREP_SMEM);
    cudaFuncSetAttribute(scan2_kernel,
                         cudaFuncAttributeMaxDynamicSharedMemorySize, 2*256*33*4);

    wsplit_kernel<<<2048, 256>>>(Wg, WD);
    wprep_kernel<<<192, 256>>>(WA, WB, WC);
    prep_kernel<<<256, 256, PREP_SMEM>>>(x);
    scan1_kernel<<<32, 256>>>();
    scan2_kernel<<<1, 256, 2*256*33*4>>>();
    scan3_kernel<<<32, 256>>>();
    main_kernel<<<dim3(8, 256), 512, SMEM_BYTES>>>(bD, bg, out);
}

// round 11
// speedup vs baseline: 9.4111x; 1.0126x over previous
#include <cuda_runtime.h>
#include <cuda_fp16.h>
#include <math.h>
#include <stdint.h>

#define BB 16
#define SS 2048
#define DD 1024
#define NN 16
#define M_TOT (BB*SS)   // 32768 tokens

// ---------------- scratch (__device__ globals) ------------------------------
__device__ __align__(256) float g_a[M_TOT*NN];
__device__ __align__(256) float g_b[M_TOT*NN];
__device__ __align__(256) __half g_hhi[M_TOT*NN];
__device__ __align__(256) __half g_hlo[M_TOT*NN];
__device__ __align__(256) __half g_xhi[(size_t)M_TOT*DD];
__device__ __align__(256) __half g_whi[2048*DD];
__device__ __align__(256) __half g_wabhi[32*DD];
__device__ __align__(256) __half g_wablo[32*DD];
__device__ __align__(256) __half g_wchi[DD*NN];
__device__ __align__(256) __half g_wclo[DD*NN];
__device__ float g_Ac[256*64];
__device__ float g_Bc[256*64];
__device__ float g_carry[256*64];

// ---------------- PTX helpers ----------------------------------------------
__device__ __forceinline__ uint32_t smem_u32(const void* p) {
    uint32_t a;
    asm("{ .reg .u64 t; cvta.to.shared.u64 t, %1; cvt.u32.u64 %0, t; }" : "=r"(a) : "l"(p));
    return a;
}
__device__ __forceinline__ void cp16(uint32_t dst, const void* src) {
    asm volatile("cp.async.cg.shared.global [%0], [%1], 16;" :: "r"(dst), "l"(src) : "memory");
}
#define CP_COMMIT() asm volatile("cp.async.commit_group;" ::: "memory")
#define CP_WAIT2()  asm volatile("cp.async.wait_group 2;" ::: "memory")
#define CP_WAIT1()  asm volatile("cp.async.wait_group 1;" ::: "memory")
#define CP_WAIT0()  asm volatile("cp.async.wait_group 0;" ::: "memory")

__device__ __forceinline__ void ldsm4(uint32_t* r, uint32_t addr) {
    asm volatile("ldmatrix.sync.aligned.m8n8.x4.shared.b16 {%0,%1,%2,%3}, [%4];"
                 : "=r"(r[0]), "=r"(r[1]), "=r"(r[2]), "=r"(r[3]) : "r"(addr));
}
__device__ __forceinline__ void mma16816(float* d, const uint32_t* a, const uint32_t* b) {
    asm volatile("mma.sync.aligned.m16n8k16.row.col.f32.f16.f16.f32 "
                 "{%0,%1,%2,%3}, {%4,%5,%6,%7}, {%8,%9}, {%0,%1,%2,%3};"
                 : "+f"(d[0]), "+f"(d[1]), "+f"(d[2]), "+f"(d[3])
                 : "r"(a[0]), "r"(a[1]), "r"(a[2]), "r"(a[3]), "r"(b[0]), "r"(b[1]));
}

// ---------------------------------------------------------------------------
// wfuse: blocks < 2048: W pair-interleave -> g_whi; blocks >= 2048: WA/WB/WC
// ---------------------------------------------------------------------------
__global__ __launch_bounds__(256) void wfuse_kernel(const float* __restrict__ Wg,
                                                    const float* __restrict__ WD,
                                                    const float* __restrict__ WA,
                                                    const float* __restrict__ WB,
                                                    const float* __restrict__ WC)
{
    int bx = blockIdx.x;
    if (bx < 2048) {
        int idx = bx * 256 + threadIdx.x;
        int r  = idx >> 8;
        int c4 = idx & 255;
        int j = r >> 8, q = r & 255;
        int p = q >> 4, s = q & 15;
        int e = j*128 + p*8 + (s & 7);
        const float* src = (s < 8) ? (Wg + (size_t)e * DD) : (WD + (size_t)e * DD);
        float4 v = ((const float4*)src)[c4];
        __half2 hA = __floats2half2_rn(v.x, v.y);
        __half2 hB = __floats2half2_rn(v.z, v.w);
        uint2 hp;
        hp.x = *(uint32_t*)&hA; hp.y = *(uint32_t*)&hB;
        *(uint2*)(g_whi + (size_t)r * DD + c4 * 4) = hp;
    } else {
        int id = (bx - 2048) * 256 + threadIdx.x;   // 192 blocks -> 49152
        float v;
        if (id < 32768) {
            int r = id >> 10, c = id & 1023;
            v = (r < 16) ? WA[(size_t)r * DD + c] : WB[(size_t)(r - 16) * DD + c];
            __half h = __float2half_rn(v);
            g_wabhi[id] = h;
            g_wablo[id] = __float2half_rn(v - __half2float(h));
        } else {
            int i2 = id - 32768;
            v = WC[i2];
            __half h = __float2half_rn(v);
            g_wchi[i2] = h;
            g_wclo[i2] = __float2half_rn(v - __half2float(h));
        }
    }
}

// ---------------------------------------------------------------------------
// prep: W resident in smem, double-buffered x staging, overlapped cp.async.
// a=tanh(x@WA^T), b=x@WB^T via 3-term fp16 HMMA; writes g_xhi.
// x staging stride = 256 B (16B-aligned; quarter-warp phases make the
// float4 read-back conflict-free, no pad needed).
// ---------------------------------------------------------------------------
#define PXF0 0
#define PXF1 32768
#define PXH  65536
#define PXL  81920
#define PWH  98304
#define PWL  163840
#define PREP_SMEM 229376
#define PXFS 256

__global__ __launch_bounds__(256) void prep_kernel(const float* __restrict__ x)
{
    extern __shared__ char smem[];
    uint32_t sb = smem_u32(smem);
    const int tid  = threadIdx.x;
    const int lane = tid & 31;
    const int wid  = tid >> 5;
    const int m0   = blockIdx.x * 128;
    const uint32_t lh = lane & 7;

    // W resident: 16 chunk-tiles (32 rows x 64 cols each), hi + lo
    #pragma unroll
    for (int i = 0; i < 16; i++) {
        int u = tid + i * 256;            // 0..4095
        int c = u >> 8, v = u & 255, row = v >> 3, c16 = v & 7;
        uint32_t off = (uint32_t)(c * 4096 + row * 128 + ((c16 ^ (row & 7)) << 4));
        const size_t gs = (size_t)row * DD + c * 64 + c16 * 8;
        cp16(sb + PWH + off, g_wabhi + gs);
        cp16(sb + PWL + off, g_wablo + gs);
    }
    CP_COMMIT();
    // x chunk 0
    #pragma unroll
    for (int i = 0; i < 8; i++) {
        int u = tid + i * 256;
        int row = u >> 4, q = u & 15;
        cp16(sb + PXF0 + row * PXFS + q * 16, x + (size_t)(m0 + row) * DD + q * 4);
    }
    CP_COMMIT();

    float acc[4][4] = {};

    for (int kc = 0; kc < 16; kc++) {
        CP_WAIT0();                        // x chunk kc (+ W at kc=0)
        // issue x chunk kc+1 (overlaps convert + mma below)
        if (kc < 15) {
            uint32_t nbuf = ((kc + 1) & 1) ? PXF1 : PXF0;
            #pragma unroll
            for (int i = 0; i < 8; i++) {
                int u = tid + i * 256;
                int row = u >> 4, q = u & 15;
                cp16(sb + nbuf + row * PXFS + q * 16,
                     x + (size_t)(m0 + row) * DD + (kc + 1) * 64 + q * 4);
            }
            CP_COMMIT();
        }
        // convert own-copied elements (thread-local cp.async visibility)
        uint32_t pxf = (kc & 1) ? PXF1 : PXF0;
        #pragma unroll
        for (int i = 0; i < 8; i++) {
            int u = tid + i * 256;
            int row = u >> 4, q = u & 15;
            float4 v = *(const float4*)(smem + pxf + row * PXFS + q * 16);
            __half hx = __float2half_rn(v.x), hy = __float2half_rn(v.y);
            __half hz = __float2half_rn(v.z), hw = __float2half_rn(v.w);
            __half2 hA = __halves2half2(hx, hy), hB = __halves2half2(hz, hw);
            __half2 lA = __floats2half2_rn(v.x - __half2float(hx), v.y - __half2float(hy));
            __half2 lB = __floats2half2_rn(v.z - __half2float(hz), v.w - __half2float(hw));
            uint2 hp, lp;
            hp.x = *(uint32_t*)&hA; hp.y = *(uint32_t*)&hB;
            lp.x = *(uint32_t*)&lA; lp.y = *(uint32_t*)&lB;
            int c16 = q >> 1;
            uint32_t soff = row * 128 + (((uint32_t)c16 ^ (row & 7)) << 4) + (q & 1) * 8;
            *(uint2*)(smem + PXH + soff) = hp;
            *(uint2*)(smem + PXL + soff) = lp;
            *(uint2*)(g_xhi + (size_t)(m0 + row) * DD + kc * 64 + q * 4) = hp;
        }
        __syncthreads();

        const uint32_t aBase = (uint32_t)((wid * 16 + (lane & 15)) * 128);
        const uint32_t bRow  = (uint32_t)(((lane >> 4) << 3) + lh);
        const uint32_t wchk  = (uint32_t)(kc * 4096);
        #pragma unroll
        for (int kk = 0; kk < 4; kk++) {
            uint32_t aSw = (((uint32_t)(kk*2) + (lane >> 4)) ^ lh) << 4;
            uint32_t bSw = (((uint32_t)(kk*2) + ((lane >> 3) & 1)) ^ lh) << 4;
            uint32_t ah[4], al[4], bh[8], bl[8];
            ldsm4(ah, sb + PXH + aBase + aSw);
            ldsm4(al, sb + PXL + aBase + aSw);
            ldsm4(&bh[0], sb + PWH + wchk + bRow * 128 + bSw);
            ldsm4(&bh[4], sb + PWH + wchk + (bRow + 16) * 128 + bSw);
            ldsm4(&bl[0], sb + PWL + wchk + bRow * 128 + bSw);
            ldsm4(&bl[4], sb + PWL + wchk + (bRow + 16) * 128 + bSw);
            #pragma unroll
            for (int ni = 0; ni < 4; ni++) {
                mma16816(acc[ni], ah, &bh[ni*2]);
                mma16816(acc[ni], ah, &bl[ni*2]);
                mma16816(acc[ni], al, &bh[ni*2]);
            }
        }
        __syncthreads();
    }

    #pragma unroll
    for (int ni = 0; ni < 4; ni++) {
        #pragma unroll
        for (int fr = 0; fr < 4; fr++) {
            int row = m0 + wid*16 + (lane >> 2) + (fr >> 1) * 8;
            int col = ni*8 + (lane & 3) * 2 + (fr & 1);
            float v = acc[ni][fr];
            if (col < 16) g_a[(size_t)row * NN + col]        = tanhf(v);
            else          g_b[(size_t)row * NN + (col - 16)] = v;
        }
    }
}

// ---------------------------------------------------------------------------
// Parallel scan: 64 chunks x 32 steps, 256 chains
// ---------------------------------------------------------------------------
__global__ __launch_bounds__(256) void scan1_kernel()
{
    int id = blockIdx.x * 256 + threadIdx.x;      // 16384
    int n = id & 15, ch = (id >> 4) & 63, b = id >> 10;
    float A = 1.0f, h = 0.0f;
    size_t base = ((size_t)b * SS + ch * 32) * NN + n;
    #pragma unroll 4
    for (int i = 0; i < 32; i++) {
        float av = g_a[base + (size_t)i * NN];
        float bv = g_b[base + (size_t)i * NN];
        A *= av;
        h = fmaf(av, h, bv);
    }
    g_Ac[(b*16 + n)*64 + ch] = A;
    g_Bc[(b*16 + n)*64 + ch] = h;
}
__global__ __launch_bounds__(256) void scan2_kernel()
{
    extern __shared__ float s2[];                 // sA[256*65] | sB[256*65]
    float* sA = s2;
    float* sB = s2 + 256*65;
    const int tid = threadIdx.x;
    #pragma unroll
    for (int i = 0; i < 64; i++) {
        int idx = i * 256 + tid;                  // 16384
        int chain = idx >> 6, c = idx & 63;
        sA[chain*65 + c] = g_Ac[idx];
        sB[chain*65 + c] = g_Bc[idx];
    }
    __syncthreads();
    float carry = 0.0f;
    #pragma unroll
    for (int c = 0; c < 64; c++) {
        g_carry[tid*64 + c] = carry;
        carry = fmaf(sA[tid*65 + c], carry, sB[tid*65 + c]);
    }
}
__global__ __launch_bounds__(256) void scan3_kernel()
{
    int id = blockIdx.x * 256 + threadIdx.x;
    int n = id & 15, ch = (id >> 4) & 63, b = id >> 10;
    float h = g_carry[(b*16 + n)*64 + ch];
    size_t base = ((size_t)b * SS + ch * 32) * NN + n;
    #pragma unroll 4
    for (int i = 0; i < 32; i++) {
        size_t idx = base + (size_t)i * NN;
        h = fmaf(g_a[idx], h, g_b[idx]);
        __half hh = __float2half_rn(h);
        g_hhi[idx] = hh;
        g_hlo[idx] = __float2half_rn(h - __half2float(hh));
    }
}

// ---------------------------------------------------------------------------
// Main: CTA 128x256, 512 thr, grid (8, 256). Single-term fp16, 4-stage ring,
// 1 sync/chunk. Gate/skip pair-interleaved -> full register epilogue.
// ---------------------------------------------------------------------------
#define STG      49152               // A 16K | W 32K
#define SW       16384
#define HT_OFF   (4*STG)             // 196608: hhi|hlo|wchi|wclo 4x4096
#define SMEM_BYTES (HT_OFF + 16384)  // 212992
#define NCH 16

__device__ __forceinline__ void load_chunk(uint32_t sb, int c, int m0, int jw, int tid)
{
    int kc = c * 64;
    uint32_t buf = sb + (uint32_t)(c & 3) * STG;
    #pragma unroll
    for (int i = 0; i < 6; i++) {
        int u = tid + i * 512;        // 3072 cp16
        if (u < 1024) {               // A: 128 rows x 8 c16
            int row = u >> 3, c16 = u & 7;
            cp16(buf + row * 128 + ((c16 ^ (row & 7)) << 4),
                 g_xhi + (size_t)(m0 + row) * DD + kc + c16 * 8);
        } else {                      // W: 256 rows x 8 c16
            int v = u - 1024;
            int row = v >> 3, c16 = v & 7;
            cp16(buf + SW + row * 128 + ((c16 ^ (row & 7)) << 4),
                 g_whi + (size_t)(jw + row) * DD + kc + c16 * 8);
        }
    }
    CP_COMMIT();
}

__global__ __launch_bounds__(512) void main_kernel(const float* __restrict__ bD,
                                                   const float* __restrict__ bg,
                                                   float* __restrict__ out)
{
    extern __shared__ char smem[];
    uint32_t sb = smem_u32(smem);
    const int tid    = threadIdx.x;
    const int lane   = tid & 31;
    const int wid    = tid >> 5;
    const int warp_m = wid & 1;       // 2 m-groups of 64 rows
    const int warp_n = wid >> 1;      // 8 n-groups of 32 cols
    const int j  = blockIdx.x;        // 0..7
    const int m0 = blockIdx.y * 128;
    const int jw = j * 256;
    const uint32_t lh = lane & 7;

    // HT tiles: hhi|hlo (128x16), wchi|wclo (128x16) -> 1024 cp16
    #pragma unroll
    for (int i = 0; i < 2; i++) {
        int u = tid + i * 512;
        int region = u >> 8, v = u & 255;
        int row = v >> 1, c16 = v & 1;
        const __half* src;
        if      (region == 0) src = g_hhi  + (size_t)(m0 + row) * NN + c16 * 8;
        else if (region == 1) src = g_hlo  + (size_t)(m0 + row) * NN + c16 * 8;
        else if (region == 2) src = g_wchi + (size_t)(j*128 + row) * NN + c16 * 8;
        else                  src = g_wclo + (size_t)(j*128 + row) * NN + c16 * 8;
        cp16(sb + HT_OFF + region * 4096 + row * 32 + c16 * 16, src);
    }
    load_chunk(sb, 0, m0, jw, tid);   // group 0 (includes HT)
    load_chunk(sb, 1, m0, jw, tid);   // group 1
    load_chunk(sb, 2, m0, jw, tid);   // group 2

    float d[4][4][4] = {};

    const uint32_t aBase = (uint32_t)((warp_m*64 + (lane & 15)) * 128);
    const uint32_t aHalf = (uint32_t)(lane >> 4);
    const uint32_t bBase = (uint32_t)(SW + (warp_n*32 + ((lane >> 4) << 3) + lh) * 128);
    const uint32_t bHalf = (uint32_t)((lane >> 3) & 1);

    for (int c = 0; c < NCH; c++) {
        if      (c + 1 == NCH) CP_WAIT0();
        else if (c + 2 == NCH) CP_WAIT1();
        else                   CP_WAIT2();
        __syncthreads();
        if (c + 3 < NCH) load_chunk(sb, c + 3, m0, jw, tid);

        uint32_t buf = sb + (uint32_t)(c & 3) * STG;
        #pragma unroll
        for (int kk = 0; kk < 4; kk++) {
            uint32_t aSw = (((uint32_t)(kk*2) + aHalf) ^ lh) << 4;
            uint32_t bSw = (((uint32_t)(kk*2) + bHalf) ^ lh) << 4;
            uint32_t b[8], a[4][4];
            ldsm4(&b[0], buf + bBase + bSw);
            ldsm4(&b[4], buf + bBase + 2048 + bSw);
            #pragma unroll
            for (int mi = 0; mi < 4; mi++)
                ldsm4(a[mi], buf + aBase + mi * 2048 + aSw);
            #pragma unroll
            for (int mi = 0; mi < 4; mi++)
                #pragma unroll
                for (int ni = 0; ni < 4; ni++)
                    mma16816(d[mi][ni], a[mi], &b[ni*2]);
        }
    }

    // ---- register epilogue: y = hs@WC^T (3-term fp16), then gating ----
    uint32_t bh[4], bl[4];
    const uint32_t bO = sb + HT_OFF + 8192 +
        (uint32_t)((warp_n*16 + ((lane >> 4) << 3) + lh) * 32 + ((lane >> 3) & 1) * 16);
    ldsm4(bh, bO);
    ldsm4(bl, bO + 4096);
    const uint32_t aO = sb + HT_OFF +
        (uint32_t)((warp_m*64 + (lane & 15)) * 32 + (lane >> 4) * 16);

    const int ecol = j*128 + warp_n*16 + (lane & 3) * 2;
    const float2 bg0 = *(const float2*)(bg + ecol);
    const float2 bg1 = *(const float2*)(bg + ecol + 8);
    const float2 bd0 = *(const float2*)(bD + ecol);
    const float2 bd1 = *(const float2*)(bD + ecol + 8);

    #pragma unroll
    for (int mi = 0; mi < 4; mi++) {
        uint32_t ah[4], al[4];
        ldsm4(ah, aO + mi * 512);
        ldsm4(al, aO + 4096 + mi * 512);
        float ya[2][4] = {};
        #pragma unroll
        for (int nj = 0; nj < 2; nj++) {
            mma16816(ya[nj], ah, &bh[nj*2]);
            mma16816(ya[nj], ah, &bl[nj*2]);
            mma16816(ya[nj], al, &bh[nj*2]);
        }
        #pragma unroll
        for (int nj = 0; nj < 2; nj++) {
            float2 bgv = nj ? bg1 : bg0;
            float2 bdv = nj ? bd1 : bd0;
            #pragma unroll
            for (int hl = 0; hl < 2; hl++) {
                int row = m0 + warp_m*64 + mi*16 + (lane >> 2) + hl*8;
                float g0 = 1.0f / (1.0f + __expf(-(d[mi][2*nj][hl*2+0] + bgv.x)));
                float g1 = 1.0f / (1.0f + __expf(-(d[mi][2*nj][hl*2+1] + bgv.y)));
                float x0 = d[mi][2*nj+1][hl*2+0] + bdv.x;
                float x1 = d[mi][2*nj+1][hl*2+1] + bdv.y;
                float2 o;
                o.x = ya[nj][hl*2+0] * g0 + x0 * (1.0f - g0);
                o.y = ya[nj][hl*2+1] * g1 + x1 * (1.0f - g1);
                *(float2*)(out + (size_t)row * DD + ecol + nj*8) = o;
            }
        }
    }
}

// ---------------------------------------------------------------------------
extern "C" void kernel_launch(void* const* d_in, const int* in_sizes, int n_in,
                              void* d_out, int out_size)
{
    const float* x  = (const float*)d_in[0];
    const float* WA = (const float*)d_in[1];
    const float* WB = (const float*)d_in[2];
    const float* WC = (const float*)d_in[3];
    const float* WD = (const float*)d_in[4];
    const float* bD = (const float*)d_in[5];
    const float* Wg = (const float*)d_in[6];
    const float* bg = (const float*)d_in[7];
    float* out = (float*)d_out;

    cudaFuncSetAttribute(main_kernel,
                         cudaFuncAttributeMaxDynamicSharedMemorySize, SMEM_BYTES);
    cudaFuncSetAttribute(prep_kernel,
                         cudaFuncAttributeMaxDynamicSharedMemorySize, PREP_SMEM);
    cudaFuncSetAttribute(scan2_kernel,
                         cudaFuncAttributeMaxDynamicSharedMemorySize, 2*256*65*4);

    wfuse_kernel<<<2240, 256>>>(Wg, WD, WA, WB, WC);
    prep_kernel<<<256, 256, PREP_SMEM>>>(x);
    scan1_kernel<<<64, 256>>>();
    scan2_kernel<<<1, 256, 2*256*65*4>>>();
    scan3_kernel<<<64, 256>>>();
    main_kernel<<<dim3(8, 256), 512, SMEM_BYTES>>>(bD, bg, out);
}

// round 12
// speedup vs baseline: 9.5296x; 1.0126x over previous
#include <cuda_runtime.h>
#include <cuda_fp16.h>
#include <math.h>
#include <stdint.h>

#define BB 16
#define SS 2048
#define DD 1024
#define NN 16
#define M_TOT (BB*SS)   // 32768 tokens

// ---------------- scratch (__device__ globals) ------------------------------
__device__ __align__(256) float g_a[M_TOT*NN];
__device__ __align__(256) float g_b[M_TOT*NN];
__device__ __align__(256) __half g_hhi[M_TOT*NN];
__device__ __align__(256) __half g_hlo[M_TOT*NN];
__device__ __align__(256) __half g_xhi[(size_t)M_TOT*DD];
__device__ __align__(256) __half g_whi[2048*DD];
__device__ __align__(256) __half g_wabhi[32*DD];
__device__ __align__(256) __half g_wablo[32*DD];
__device__ __align__(256) __half g_wchi[DD*NN];
__device__ __align__(256) __half g_wclo[DD*NN];

// ---------------- PTX helpers ----------------------------------------------
__device__ __forceinline__ uint32_t smem_u32(const void* p) {
    uint32_t a;
    asm("{ .reg .u64 t; cvta.to.shared.u64 t, %1; cvt.u32.u64 %0, t; }" : "=r"(a) : "l"(p));
    return a;
}
__device__ __forceinline__ void cp16(uint32_t dst, const void* src) {
    asm volatile("cp.async.cg.shared.global [%0], [%1], 16;" :: "r"(dst), "l"(src) : "memory");
}
#define CP_COMMIT() asm volatile("cp.async.commit_group;" ::: "memory")
#define CP_WAIT2()  asm volatile("cp.async.wait_group 2;" ::: "memory")
#define CP_WAIT1()  asm volatile("cp.async.wait_group 1;" ::: "memory")
#define CP_WAIT0()  asm volatile("cp.async.wait_group 0;" ::: "memory")

__device__ __forceinline__ void ldsm4(uint32_t* r, uint32_t addr) {
    asm volatile("ldmatrix.sync.aligned.m8n8.x4.shared.b16 {%0,%1,%2,%3}, [%4];"
                 : "=r"(r[0]), "=r"(r[1]), "=r"(r[2]), "=r"(r[3]) : "r"(addr));
}
__device__ __forceinline__ void mma16816(float* d, const uint32_t* a, const uint32_t* b) {
    asm volatile("mma.sync.aligned.m16n8k16.row.col.f32.f16.f16.f32 "
                 "{%0,%1,%2,%3}, {%4,%5,%6,%7}, {%8,%9}, {%0,%1,%2,%3};"
                 : "+f"(d[0]), "+f"(d[1]), "+f"(d[2]), "+f"(d[3])
                 : "r"(a[0]), "r"(a[1]), "r"(a[2]), "r"(a[3]), "r"(b[0]), "r"(b[1]));
}

// ---------------------------------------------------------------------------
// wfuse: blocks < 2048: W pair-interleave -> g_whi; blocks >= 2048: WA/WB/WC
// ---------------------------------------------------------------------------
__global__ __launch_bounds__(256) void wfuse_kernel(const float* __restrict__ Wg,
                                                    const float* __restrict__ WD,
                                                    const float* __restrict__ WA,
                                                    const float* __restrict__ WB,
                                                    const float* __restrict__ WC)
{
    int bx = blockIdx.x;
    if (bx < 2048) {
        int idx = bx * 256 + threadIdx.x;
        int r  = idx >> 8;
        int c4 = idx & 255;
        int j = r >> 8, q = r & 255;
        int p = q >> 4, s = q & 15;
        int e = j*128 + p*8 + (s & 7);
        const float* src = (s < 8) ? (Wg + (size_t)e * DD) : (WD + (size_t)e * DD);
        float4 v = ((const float4*)src)[c4];
        __half2 hA = __floats2half2_rn(v.x, v.y);
        __half2 hB = __floats2half2_rn(v.z, v.w);
        uint2 hp;
        hp.x = *(uint32_t*)&hA; hp.y = *(uint32_t*)&hB;
        *(uint2*)(g_whi + (size_t)r * DD + c4 * 4) = hp;
    } else {
        int id = (bx - 2048) * 256 + threadIdx.x;   // 192 blocks -> 49152
        float v;
        if (id < 32768) {
            int r = id >> 10, c = id & 1023;
            v = (r < 16) ? WA[(size_t)r * DD + c] : WB[(size_t)(r - 16) * DD + c];
            __half h = __float2half_rn(v);
            g_wabhi[id] = h;
            g_wablo[id] = __float2half_rn(v - __half2float(h));
        } else {
            int i2 = id - 32768;
            v = WC[i2];
            __half h = __float2half_rn(v);
            g_wchi[i2] = h;
            g_wclo[i2] = __float2half_rn(v - __half2float(h));
        }
    }
}

// ---------------------------------------------------------------------------
// prep: W resident in smem, double-buffered x staging, overlapped cp.async.
// a=tanh(x@WA^T), b=x@WB^T via 3-term fp16 HMMA; writes g_xhi.
// ---------------------------------------------------------------------------
#define PXF0 0
#define PXF1 32768
#define PXH  65536
#define PXL  81920
#define PWH  98304
#define PWL  163840
#define PREP_SMEM 229376
#define PXFS 256

__global__ __launch_bounds__(256) void prep_kernel(const float* __restrict__ x)
{
    extern __shared__ char smem[];
    uint32_t sb = smem_u32(smem);
    const int tid  = threadIdx.x;
    const int lane = tid & 31;
    const int wid  = tid >> 5;
    const int m0   = blockIdx.x * 128;
    const uint32_t lh = lane & 7;

    // W resident: 16 chunk-tiles (32 rows x 64 cols each), hi + lo
    #pragma unroll
    for (int i = 0; i < 16; i++) {
        int u = tid + i * 256;            // 0..4095
        int c = u >> 8, v = u & 255, row = v >> 3, c16 = v & 7;
        uint32_t off = (uint32_t)(c * 4096 + row * 128 + ((c16 ^ (row & 7)) << 4));
        const size_t gs = (size_t)row * DD + c * 64 + c16 * 8;
        cp16(sb + PWH + off, g_wabhi + gs);
        cp16(sb + PWL + off, g_wablo + gs);
    }
    CP_COMMIT();
    // x chunk 0
    #pragma unroll
    for (int i = 0; i < 8; i++) {
        int u = tid + i * 256;
        int row = u >> 4, q = u & 15;
        cp16(sb + PXF0 + row * PXFS + q * 16, x + (size_t)(m0 + row) * DD + q * 4);
    }
    CP_COMMIT();

    float acc[4][4] = {};

    for (int kc = 0; kc < 16; kc++) {
        CP_WAIT0();                        // x chunk kc (+ W at kc=0)
        // issue x chunk kc+1 (overlaps convert + mma below)
        if (kc < 15) {
            uint32_t nbuf = ((kc + 1) & 1) ? PXF1 : PXF0;
            #pragma unroll
            for (int i = 0; i < 8; i++) {
                int u = tid + i * 256;
                int row = u >> 4, q = u & 15;
                cp16(sb + nbuf + row * PXFS + q * 16,
                     x + (size_t)(m0 + row) * DD + (kc + 1) * 64 + q * 4);
            }
            CP_COMMIT();
        }
        // convert own-copied elements (thread-local cp.async visibility)
        uint32_t pxf = (kc & 1) ? PXF1 : PXF0;
        #pragma unroll
        for (int i = 0; i < 8; i++) {
            int u = tid + i * 256;
            int row = u >> 4, q = u & 15;
            float4 v = *(const float4*)(smem + pxf + row * PXFS + q * 16);
            __half hx = __float2half_rn(v.x), hy = __float2half_rn(v.y);
            __half hz = __float2half_rn(v.z), hw = __float2half_rn(v.w);
            __half2 hA = __halves2half2(hx, hy), hB = __halves2half2(hz, hw);
            __half2 lA = __floats2half2_rn(v.x - __half2float(hx), v.y - __half2float(hy));
            __half2 lB = __floats2half2_rn(v.z - __half2float(hz), v.w - __half2float(hw));
            uint2 hp, lp;
            hp.x = *(uint32_t*)&hA; hp.y = *(uint32_t*)&hB;
            lp.x = *(uint32_t*)&lA; lp.y = *(uint32_t*)&lB;
            int c16 = q >> 1;
            uint32_t soff = row * 128 + (((uint32_t)c16 ^ (row & 7)) << 4) + (q & 1) * 8;
            *(uint2*)(smem + PXH + soff) = hp;
            *(uint2*)(smem + PXL + soff) = lp;
            *(uint2*)(g_xhi + (size_t)(m0 + row) * DD + kc * 64 + q * 4) = hp;
        }
        __syncthreads();

        const uint32_t aBase = (uint32_t)((wid * 16 + (lane & 15)) * 128);
        const uint32_t bRow  = (uint32_t)(((lane >> 4) << 3) + lh);
        const uint32_t wchk  = (uint32_t)(kc * 4096);
        #pragma unroll
        for (int kk = 0; kk < 4; kk++) {
            uint32_t aSw = (((uint32_t)(kk*2) + (lane >> 4)) ^ lh) << 4;
            uint32_t bSw = (((uint32_t)(kk*2) + ((lane >> 3) & 1)) ^ lh) << 4;
            uint32_t ah[4], al[4], bh[8], bl[8];
            ldsm4(ah, sb + PXH + aBase + aSw);
            ldsm4(al, sb + PXL + aBase + aSw);
            ldsm4(&bh[0], sb + PWH + wchk + bRow * 128 + bSw);
            ldsm4(&bh[4], sb + PWH + wchk + (bRow + 16) * 128 + bSw);
            ldsm4(&bl[0], sb + PWL + wchk + bRow * 128 + bSw);
            ldsm4(&bl[4], sb + PWL + wchk + (bRow + 16) * 128 + bSw);
            #pragma unroll
            for (int ni = 0; ni < 4; ni++) {
                mma16816(acc[ni], ah, &bh[ni*2]);
                mma16816(acc[ni], ah, &bl[ni*2]);
                mma16816(acc[ni], al, &bh[ni*2]);
            }
        }
        __syncthreads();
    }

    #pragma unroll
    for (int ni = 0; ni < 4; ni++) {
        #pragma unroll
        for (int fr = 0; fr < 4; fr++) {
            int row = m0 + wid*16 + (lane >> 2) + (fr >> 1) * 8;
            int col = ni*8 + (lane & 3) * 2 + (fr & 1);
            float v = acc[ni][fr];
            if (col < 16) g_a[(size_t)row * NN + col]        = tanhf(v);
            else          g_b[(size_t)row * NN + (col - 16)] = v;
        }
    }
}

// ---------------------------------------------------------------------------
// Fused scan: ONE kernel, grid 16 (one block per batch), 512 threads
// = 16 chains x 32 chunks of 64 steps. Phase1: per-thread chunk scan (A,B).
// Phase2: 16 threads serial-prefix 32 chunks in smem ((A,B) op is assoc.).
// Phase3: rescan with carry, emit fp16 hi/lo of h.
// ---------------------------------------------------------------------------
__global__ __launch_bounds__(512) void scanf_kernel()
{
    __shared__ float sA[16*33];
    __shared__ float sB[16*33];
    const int tid = threadIdx.x;
    const int n  = tid & 15;
    const int ch = tid >> 4;          // 0..31
    const int b  = blockIdx.x;
    const size_t base = ((size_t)b * SS + ch * 64) * NN + n;

    // Phase 1: chunk-local (A, B)
    float A = 1.0f, h = 0.0f;
    #pragma unroll 4
    for (int i = 0; i < 64; i++) {
        float av = g_a[base + (size_t)i * NN];
        float bv = g_b[base + (size_t)i * NN];
        A *= av;
        h = fmaf(av, h, bv);
    }
    sA[n*33 + ch] = A;
    sB[n*33 + ch] = h;
    __syncthreads();

    // Phase 2: serial prefix over 32 chunks per chain (16 threads)
    if (tid < 16) {
        float carry = 0.0f;
        #pragma unroll
        for (int c = 0; c < 32; c++) {
            float a2 = sA[tid*33 + c];
            float b2 = sB[tid*33 + c];
            sB[tid*33 + c] = carry;          // carry-in for chunk c
            carry = fmaf(a2, carry, b2);
        }
    }
    __syncthreads();

    // Phase 3: rescan with carry, write h hi/lo
    h = sB[n*33 + ch];
    #pragma unroll 4
    for (int i = 0; i < 64; i++) {
        size_t idx = base + (size_t)i * NN;
        h = fmaf(g_a[idx], h, g_b[idx]);
        __half hh = __float2half_rn(h);
        g_hhi[idx] = hh;
        g_hlo[idx] = __float2half_rn(h - __half2float(hh));
    }
}

// ---------------------------------------------------------------------------
// Main: CTA 128x256, 512 thr, grid (8, 256). Single-term fp16, 4-stage ring,
// 1 sync/chunk. Gate/skip pair-interleaved -> full register epilogue.
// ---------------------------------------------------------------------------
#define STG      49152               // A 16K | W 32K
#define SW       16384
#define HT_OFF   (4*STG)             // 196608: hhi|hlo|wchi|wclo 4x4096
#define SMEM_BYTES (HT_OFF + 16384)  // 212992
#define NCH 16

__device__ __forceinline__ void load_chunk(uint32_t sb, int c, int m0, int jw, int tid)
{
    int kc = c * 64;
    uint32_t buf = sb + (uint32_t)(c & 3) * STG;
    #pragma unroll
    for (int i = 0; i < 6; i++) {
        int u = tid + i * 512;        // 3072 cp16
        if (u < 1024) {               // A: 128 rows x 8 c16
            int row = u >> 3, c16 = u & 7;
            cp16(buf + row * 128 + ((c16 ^ (row & 7)) << 4),
                 g_xhi + (size_t)(m0 + row) * DD + kc + c16 * 8);
        } else {                      // W: 256 rows x 8 c16
            int v = u - 1024;
            int row = v >> 3, c16 = v & 7;
            cp16(buf + SW + row * 128 + ((c16 ^ (row & 7)) << 4),
                 g_whi + (size_t)(jw + row) * DD + kc + c16 * 8);
        }
    }
    CP_COMMIT();
}

__global__ __launch_bounds__(512) void main_kernel(const float* __restrict__ bD,
                                                   const float* __restrict__ bg,
                                                   float* __restrict__ out)
{
    extern __shared__ char smem[];
    uint32_t sb = smem_u32(smem);
    const int tid    = threadIdx.x;
    const int lane   = tid & 31;
    const int wid    = tid >> 5;
    const int warp_m = wid & 1;       // 2 m-groups of 64 rows
    const int warp_n = wid >> 1;      // 8 n-groups of 32 cols
    const int j  = blockIdx.x;        // 0..7
    const int m0 = blockIdx.y * 128;
    const int jw = j * 256;
    const uint32_t lh = lane & 7;

    // HT tiles: hhi|hlo (128x16), wchi|wclo (128x16) -> 1024 cp16
    #pragma unroll
    for (int i = 0; i < 2; i++) {
        int u = tid + i * 512;
        int region = u >> 8, v = u & 255;
        int row = v >> 1, c16 = v & 1;
        const __half* src;
        if      (region == 0) src = g_hhi  + (size_t)(m0 + row) * NN + c16 * 8;
        else if (region == 1) src = g_hlo  + (size_t)(m0 + row) * NN + c16 * 8;
        else if (region == 2) src = g_wchi + (size_t)(j*128 + row) * NN + c16 * 8;
        else                  src = g_wclo + (size_t)(j*128 + row) * NN + c16 * 8;
        cp16(sb + HT_OFF + region * 4096 + row * 32 + c16 * 16, src);
    }
    load_chunk(sb, 0, m0, jw, tid);   // group 0 (includes HT)
    load_chunk(sb, 1, m0, jw, tid);   // group 1
    load_chunk(sb, 2, m0, jw, tid);   // group 2

    float d[4][4][4] = {};

    const uint32_t aBase = (uint32_t)((warp_m*64 + (lane & 15)) * 128);
    const uint32_t aHalf = (uint32_t)(lane >> 4);
    const uint32_t bBase = (uint32_t)(SW + (warp_n*32 + ((lane >> 4) << 3) + lh) * 128);
    const uint32_t bHalf = (uint32_t)((lane >> 3) & 1);

    for (int c = 0; c < NCH; c++) {
        if      (c + 1 == NCH) CP_WAIT0();
        else if (c + 2 == NCH) CP_WAIT1();
        else                   CP_WAIT2();
        __syncthreads();
        if (c + 3 < NCH) load_chunk(sb, c + 3, m0, jw, tid);

        uint32_t buf = sb + (uint32_t)(c & 3) * STG;
        #pragma unroll
        for (int kk = 0; kk < 4; kk++) {
            uint32_t aSw = (((uint32_t)(kk*2) + aHalf) ^ lh) << 4;
            uint32_t bSw = (((uint32_t)(kk*2) + bHalf) ^ lh) << 4;
            uint32_t b[8], a[4][4];
            ldsm4(&b[0], buf + bBase + bSw);
            ldsm4(&b[4], buf + bBase + 2048 + bSw);
            #pragma unroll
            for (int mi = 0; mi < 4; mi++)
                ldsm4(a[mi], buf + aBase + mi * 2048 + aSw);
            #pragma unroll
            for (int mi = 0; mi < 4; mi++)
                #pragma unroll
                for (int ni = 0; ni < 4; ni++)
                    mma16816(d[mi][ni], a[mi], &b[ni*2]);
        }
    }

    // ---- register epilogue: y = hs@WC^T (3-term fp16), then gating ----
    uint32_t bh[4], bl[4];
    const uint32_t bO = sb + HT_OFF + 8192 +
        (uint32_t)((warp_n*16 + ((lane >> 4) << 3) + lh) * 32 + ((lane >> 3) & 1) * 16);
    ldsm4(bh, bO);
    ldsm4(bl, bO + 4096);
    const uint32_t aO = sb + HT_OFF +
        (uint32_t)((warp_m*64 + (lane & 15)) * 32 + (lane >> 4) * 16);

    const int ecol = j*128 + warp_n*16 + (lane & 3) * 2;
    const float2 bg0 = *(const float2*)(bg + ecol);
    const float2 bg1 = *(const float2*)(bg + ecol + 8);
    const float2 bd0 = *(const float2*)(bD + ecol);
    const float2 bd1 = *(const float2*)(bD + ecol + 8);

    #pragma unroll
    for (int mi = 0; mi < 4; mi++) {
        uint32_t ah[4], al[4];
        ldsm4(ah, aO + mi * 512);
        ldsm4(al, aO + 4096 + mi * 512);
        float ya[2][4] = {};
        #pragma unroll
        for (int nj = 0; nj < 2; nj++) {
            mma16816(ya[nj], ah, &bh[nj*2]);
            mma16816(ya[nj], ah, &bl[nj*2]);
            mma16816(ya[nj], al, &bh[nj*2]);
        }
        #pragma unroll
        for (int nj = 0; nj < 2; nj++) {
            float2 bgv = nj ? bg1 : bg0;
            float2 bdv = nj ? bd1 : bd0;
            #pragma unroll
            for (int hl = 0; hl < 2; hl++) {
                int row = m0 + warp_m*64 + mi*16 + (lane >> 2) + hl*8;
                float g0 = 1.0f / (1.0f + __expf(-(d[mi][2*nj][hl*2+0] + bgv.x)));
                float g1 = 1.0f / (1.0f + __expf(-(d[mi][2*nj][hl*2+1] + bgv.y)));
                float x0 = d[mi][2*nj+1][hl*2+0] + bdv.x;
                float x1 = d[mi][2*nj+1][hl*2+1] + bdv.y;
                float2 o;
                o.x = ya[nj][hl*2+0] * g0 + x0 * (1.0f - g0);
                o.y = ya[nj][hl*2+1] * g1 + x1 * (1.0f - g1);
                *(float2*)(out + (size_t)row * DD + ecol + nj*8) = o;
            }
        }
    }
}

// ---------------------------------------------------------------------------
extern "C" void kernel_launch(void* const* d_in, const int* in_sizes, int n_in,
                              void* d_out, int out_size)
{
    const float* x  = (const float*)d_in[0];
    const float* WA = (const float*)d_in[1];
    const float* WB = (const float*)d_in[2];
    const float* WC = (const float*)d_in[3];
    const float* WD = (const float*)d_in[4];
    const float* bD = (const float*)d_in[5];
    const float* Wg = (const float*)d_in[6];
    const float* bg = (const float*)d_in[7];
    float* out = (float*)d_out;

    cudaFuncSetAttribute(main_kernel,
                         cudaFuncAttributeMaxDynamicSharedMemorySize, SMEM_BYTES);
    cudaFuncSetAttribute(prep_kernel,
                         cudaFuncAttributeMaxDynamicSharedMemorySize, PREP_SMEM);

    wfuse_kernel<<<2240, 256>>>(Wg, WD, WA, WB, WC);
    prep_kernel<<<256, 256, PREP_SMEM>>>(x);
    scanf_kernel<<<16, 512>>>();
    main_kernel<<<dim3(8, 256), 512, SMEM_BYTES>>>(bD, bg, out);
}

// round 14
// speedup vs baseline: 10.0727x; 1.0570x over previous
#include <cuda_runtime.h>
#include <cuda_fp16.h>
#include <math.h>
#include <stdint.h>

#define BB 16
#define SS 2048
#define DD 1024
#define NN 16
#define M_TOT (BB*SS)   // 32768 tokens

// ---------------- scratch (__device__ globals) ------------------------------
__device__ __align__(256) float g_a[M_TOT*NN];
__device__ __align__(256) float g_b[M_TOT*NN];
__device__ __align__(256) __half g_hhi[M_TOT*NN];
__device__ __align__(256) __half g_hlo[M_TOT*NN];
__device__ __align__(256) __half g_xhi[(size_t)M_TOT*DD];
__device__ __align__(256) __half g_whi[2048*DD];
__device__ __align__(256) __half g_wabhi[32*DD];
__device__ __align__(256) __half g_wablo[32*DD];
__device__ __align__(256) __half g_wchi[DD*NN];
__device__ __align__(256) __half g_wclo[DD*NN];

// ---------------- PTX helpers ----------------------------------------------
__device__ __forceinline__ uint32_t smem_u32(const void* p) {
    uint32_t a;
    asm("{ .reg .u64 t; cvta.to.shared.u64 t, %1; cvt.u32.u64 %0, t; }" : "=r"(a) : "l"(p));
    return a;
}
__device__ __forceinline__ void cp16(uint32_t dst, const void* src) {
    asm volatile("cp.async.cg.shared.global [%0], [%1], 16;" :: "r"(dst), "l"(src) : "memory");
}
#define CP_COMMIT() asm volatile("cp.async.commit_group;" ::: "memory")
#define CP_WAIT1()  asm volatile("cp.async.wait_group 1;" ::: "memory")
#define CP_WAIT0()  asm volatile("cp.async.wait_group 0;" ::: "memory")

__device__ __forceinline__ void ldsm4(uint32_t* r, uint32_t addr) {
    asm volatile("ldmatrix.sync.aligned.m8n8.x4.shared.b16 {%0,%1,%2,%3}, [%4];"
                 : "=r"(r[0]), "=r"(r[1]), "=r"(r[2]), "=r"(r[3]) : "r"(addr));
}
__device__ __forceinline__ void mma16816(float* d, const uint32_t* a, const uint32_t* b) {
    asm volatile("mma.sync.aligned.m16n8k16.row.col.f32.f16.f16.f32 "
                 "{%0,%1,%2,%3}, {%4,%5,%6,%7}, {%8,%9}, {%0,%1,%2,%3};"
                 : "+f"(d[0]), "+f"(d[1]), "+f"(d[2]), "+f"(d[3])
                 : "r"(a[0]), "r"(a[1]), "r"(a[2]), "r"(a[3]), "r"(b[0]), "r"(b[1]));
}

// ---------------------------------------------------------------------------
// wfuse: blocks < 2048: W pair-interleave -> g_whi; blocks >= 2048: WA/WB/WC
// ---------------------------------------------------------------------------
__global__ __launch_bounds__(256) void wfuse_kernel(const float* __restrict__ Wg,
                                                    const float* __restrict__ WD,
                                                    const float* __restrict__ WA,
                                                    const float* __restrict__ WB,
                                                    const float* __restrict__ WC)
{
    int bx = blockIdx.x;
    if (bx < 2048) {
        int idx = bx * 256 + threadIdx.x;
        int r  = idx >> 8;
        int c4 = idx & 255;
        int j = r >> 8, q = r & 255;
        int p = q >> 4, s = q & 15;
        int e = j*128 + p*8 + (s & 7);
        const float* src = (s < 8) ? (Wg + (size_t)e * DD) : (WD + (size_t)e * DD);
        float4 v = ((const float4*)src)[c4];
        __half2 hA = __floats2half2_rn(v.x, v.y);
        __half2 hB = __floats2half2_rn(v.z, v.w);
        uint2 hp;
        hp.x = *(uint32_t*)&hA; hp.y = *(uint32_t*)&hB;
        *(uint2*)(g_whi + (size_t)r * DD + c4 * 4) = hp;
    } else {
        int id = (bx - 2048) * 256 + threadIdx.x;   // 192 blocks -> 49152
        float v;
        if (id < 32768) {
            int r = id >> 10, c = id & 1023;
            v = (r < 16) ? WA[(size_t)r * DD + c] : WB[(size_t)(r - 16) * DD + c];
            __half h = __float2half_rn(v);
            g_wabhi[id] = h;
            g_wablo[id] = __float2half_rn(v - __half2float(h));
        } else {
            int i2 = id - 32768;
            v = WC[i2];
            __half h = __float2half_rn(v);
            g_wchi[i2] = h;
            g_wclo[i2] = __float2half_rn(v - __half2float(h));
        }
    }
}

// ---------------------------------------------------------------------------
// prep: W resident in smem, double-buffered x staging, overlapped cp.async.
// a=tanh(x@WA^T), b=x@WB^T via 3-term fp16 HMMA; writes g_xhi.
// ---------------------------------------------------------------------------
#define PXF0 0
#define PXF1 32768
#define PXH  65536
#define PXL  81920
#define PWH  98304
#define PWL  163840
#define PREP_SMEM 229376
#define PXFS 256

__global__ __launch_bounds__(256) void prep_kernel(const float* __restrict__ x)
{
    extern __shared__ char smem[];
    uint32_t sb = smem_u32(smem);
    const int tid  = threadIdx.x;
    const int lane = tid & 31;
    const int wid  = tid >> 5;
    const int m0   = blockIdx.x * 128;
    const uint32_t lh = lane & 7;

    // W resident: 16 chunk-tiles (32 rows x 64 cols each), hi + lo
    #pragma unroll
    for (int i = 0; i < 16; i++) {
        int u = tid + i * 256;            // 0..4095
        int c = u >> 8, v = u & 255, row = v >> 3, c16 = v & 7;
        uint32_t off = (uint32_t)(c * 4096 + row * 128 + ((c16 ^ (row & 7)) << 4));
        const size_t gs = (size_t)row * DD + c * 64 + c16 * 8;
        cp16(sb + PWH + off, g_wabhi + gs);
        cp16(sb + PWL + off, g_wablo + gs);
    }
    CP_COMMIT();
    // x chunk 0
    #pragma unroll
    for (int i = 0; i < 8; i++) {
        int u = tid + i * 256;
        int row = u >> 4, q = u & 15;
        cp16(sb + PXF0 + row * PXFS + q * 16, x + (size_t)(m0 + row) * DD + q * 4);
    }
    CP_COMMIT();

    float acc[4][4] = {};

    for (int kc = 0; kc < 16; kc++) {
        CP_WAIT0();                        // x chunk kc (+ W at kc=0)
        if (kc < 15) {
            uint32_t nbuf = ((kc + 1) & 1) ? PXF1 : PXF0;
            #pragma unroll
            for (int i = 0; i < 8; i++) {
                int u = tid + i * 256;
                int row = u >> 4, q = u & 15;
                cp16(sb + nbuf + row * PXFS + q * 16,
                     x + (size_t)(m0 + row) * DD + (kc + 1) * 64 + q * 4);
            }
            CP_COMMIT();
        }
        uint32_t pxf = (kc & 1) ? PXF1 : PXF0;
        #pragma unroll
        for (int i = 0; i < 8; i++) {
            int u = tid + i * 256;
            int row = u >> 4, q = u & 15;
            float4 v = *(const float4*)(smem + pxf + row * PXFS + q * 16);
            __half hx = __float2half_rn(v.x), hy = __float2half_rn(v.y);
            __half hz = __float2half_rn(v.z), hw = __float2half_rn(v.w);
            __half2 hA = __halves2half2(hx, hy), hB = __halves2half2(hz, hw);
            __half2 lA = __floats2half2_rn(v.x - __half2float(hx), v.y - __half2float(hy));
            __half2 lB = __floats2half2_rn(v.z - __half2float(hz), v.w - __half2float(hw));
            uint2 hp, lp;
            hp.x = *(uint32_t*)&hA; hp.y = *(uint32_t*)&hB;
            lp.x = *(uint32_t*)&lA; lp.y = *(uint32_t*)&lB;
            int c16 = q >> 1;
            uint32_t soff = row * 128 + (((uint32_t)c16 ^ (row & 7)) << 4) + (q & 1) * 8;
            *(uint2*)(smem + PXH + soff) = hp;
            *(uint2*)(smem + PXL + soff) = lp;
            *(uint2*)(g_xhi + (size_t)(m0 + row) * DD + kc * 64 + q * 4) = hp;
        }
        __syncthreads();

        const uint32_t aBase = (uint32_t)((wid * 16 + (lane & 15)) * 128);
        const uint32_t bRow  = (uint32_t)(((lane >> 4) << 3) + lh);
        const uint32_t wchk  = (uint32_t)(kc * 4096);
        #pragma unroll
        for (int kk = 0; kk < 4; kk++) {
            uint32_t aSw = (((uint32_t)(kk*2) + (lane >> 4)) ^ lh) << 4;
            uint32_t bSw = (((uint32_t)(kk*2) + ((lane >> 3) & 1)) ^ lh) << 4;
            uint32_t ah[4], al[4], bh[8], bl[8];
            ldsm4(ah, sb + PXH + aBase + aSw);
            ldsm4(al, sb + PXL + aBase + aSw);
            ldsm4(&bh[0], sb + PWH + wchk + bRow * 128 + bSw);
            ldsm4(&bh[4], sb + PWH + wchk + (bRow + 16) * 128 + bSw);
            ldsm4(&bl[0], sb + PWL + wchk + bRow * 128 + bSw);
            ldsm4(&bl[4], sb + PWL + wchk + (bRow + 16) * 128 + bSw);
            #pragma unroll
            for (int ni = 0; ni < 4; ni++) {
                mma16816(acc[ni], ah, &bh[ni*2]);
                mma16816(acc[ni], ah, &bl[ni*2]);
                mma16816(acc[ni], al, &bh[ni*2]);
            }
        }
        __syncthreads();
    }

    #pragma unroll
    for (int ni = 0; ni < 4; ni++) {
        #pragma unroll
        for (int fr = 0; fr < 4; fr++) {
            int row = m0 + wid*16 + (lane >> 2) + (fr >> 1) * 8;
            int col = ni*8 + (lane & 3) * 2 + (fr & 1);
            float v = acc[ni][fr];
            if (col < 16) g_a[(size_t)row * NN + col]        = tanhf(v);
            else          g_b[(size_t)row * NN + (col - 16)] = v;
        }
    }
}

// ---------------------------------------------------------------------------
// Fused scan: grid 16, 512 thr = 16 chains x 32 chunks of 64 steps.
// ---------------------------------------------------------------------------
__global__ __launch_bounds__(512) void scanf_kernel()
{
    __shared__ float sA[16*33];
    __shared__ float sB[16*33];
    const int tid = threadIdx.x;
    const int n  = tid & 15;
    const int ch = tid >> 4;          // 0..31
    const int b  = blockIdx.x;
    const size_t base = ((size_t)b * SS + ch * 64) * NN + n;

    float A = 1.0f, h = 0.0f;
    #pragma unroll 4
    for (int i = 0; i < 64; i++) {
        float av = g_a[base + (size_t)i * NN];
        float bv = g_b[base + (size_t)i * NN];
        A *= av;
        h = fmaf(av, h, bv);
    }
    sA[n*33 + ch] = A;
    sB[n*33 + ch] = h;
    __syncthreads();

    if (tid < 16) {
        float carry = 0.0f;
        #pragma unroll
        for (int c = 0; c < 32; c++) {
            float a2 = sA[tid*33 + c];
            float b2 = sB[tid*33 + c];
            sB[tid*33 + c] = carry;
            carry = fmaf(a2, carry, b2);
        }
    }
    __syncthreads();

    h = sB[n*33 + ch];
    #pragma unroll 4
    for (int i = 0; i < 64; i++) {
        size_t idx = base + (size_t)i * NN;
        h = fmaf(g_a[idx], h, g_b[idx]);
        __half hh = __float2half_rn(h);
        g_hhi[idx] = hh;
        g_hlo[idx] = __float2half_rn(h - __half2float(hh));
    }
}

// ---------------------------------------------------------------------------
// Main: CTA 128x128, 256 thr, grid (16, 256), 2 CTAs/SM. Single-term fp16,
// 3-stage ring (prologue {0,1}; wait1 -> sync -> prefetch c+2 -> compute c),
// register epilogue (y-GEMM + gating).
// ---------------------------------------------------------------------------
#define STG      32768               // A 16K | W 16K
#define SW       16384
#define HT_OFF   (3*STG)             // 98304: hhi(4K)|hlo(4K)|wchi(2K)|wclo(2K)
#define SMEM_BYTES (HT_OFF + 12288)  // 110592 -> 2 CTAs/SM
#define NCH 16

__device__ __forceinline__ void load_chunk(uint32_t sb, int c, int m0, int jw, int tid)
{
    int kc = c * 64;
    uint32_t buf = sb + (uint32_t)(c % 3) * STG;
    #pragma unroll
    for (int i = 0; i < 8; i++) {
        int u = tid + i * 256;        // 2048 cp16
        if (u < 1024) {               // A: 128 rows x 8 c16
            int row = u >> 3, c16 = u & 7;
            cp16(buf + row * 128 + ((c16 ^ (row & 7)) << 4),
                 g_xhi + (size_t)(m0 + row) * DD + kc + c16 * 8);
        } else {                      // W: 128 rows x 8 c16
            int v = u - 1024;
            int row = v >> 3, c16 = v & 7;
            cp16(buf + SW + row * 128 + ((c16 ^ (row & 7)) << 4),
                 g_whi + (size_t)(jw + row) * DD + kc + c16 * 8);
        }
    }
    CP_COMMIT();
}

__global__ __launch_bounds__(256, 2) void main_kernel(const float* __restrict__ bD,
                                                      const float* __restrict__ bg,
                                                      float* __restrict__ out)
{
    extern __shared__ char smem[];
    uint32_t sb = smem_u32(smem);
    const int tid    = threadIdx.x;
    const int lane   = tid & 31;
    const int wid    = tid >> 5;
    const int warp_m = wid & 1;       // 2 m-groups of 64 rows
    const int warp_n = wid >> 1;      // 4 n-groups of 32 cols
    const int j  = blockIdx.x;        // 0..15
    const int m0 = blockIdx.y * 128;
    const int jw = j * 128;
    const uint32_t lh = lane & 7;

    // HT tiles: hhi|hlo (128x16) + wchi|wclo (64x16) -> 768 cp16
    #pragma unroll
    for (int i = 0; i < 3; i++) {
        int u = tid + i * 256;            // 0..767
        const __half* src;
        uint32_t dst;
        if (u < 512) {                    // hhi / hlo
            int region = u >> 8, v = u & 255;
            int row = v >> 1, c16 = v & 1;
            src = (region == 0 ? g_hhi : g_hlo) + (size_t)(m0 + row) * NN + c16 * 8;
            dst = sb + HT_OFF + region * 4096 + row * 32 + c16 * 16;
        } else {                          // wchi / wclo
            int v = u - 512;
            int region = v >> 7, w = v & 127;
            int row = w >> 1, c16 = w & 1;
            src = (region == 0 ? g_wchi : g_wclo) + (size_t)(j*64 + row) * NN + c16 * 8;
            dst = sb + HT_OFF + 8192 + region * 2048 + row * 32 + c16 * 16;
        }
        cp16(dst, src);
    }
    load_chunk(sb, 0, m0, jw, tid);   // group 0 (includes HT)
    load_chunk(sb, 1, m0, jw, tid);   // group 1

    float d[4][4][4] = {};

    const uint32_t aBase = (uint32_t)((warp_m*64 + (lane & 15)) * 128);
    const uint32_t aHalf = (uint32_t)(lane >> 4);
    const uint32_t bBase = (uint32_t)(SW + (warp_n*32 + ((lane >> 4) << 3) + lh) * 128);
    const uint32_t bHalf = (uint32_t)((lane >> 3) & 1);

    for (int c = 0; c < NCH; c++) {
        if (c + 1 == NCH) CP_WAIT0(); else CP_WAIT1();
        __syncthreads();
        if (c + 2 < NCH) load_chunk(sb, c + 2, m0, jw, tid);

        uint32_t buf = sb + (uint32_t)(c % 3) * STG;
        #pragma unroll
        for (int kk = 0; kk < 4; kk++) {
            uint32_t aSw = (((uint32_t)(kk*2) + aHalf) ^ lh) << 4;
            uint32_t bSw = (((uint32_t)(kk*2) + bHalf) ^ lh) << 4;
            uint32_t b[8], a[4][4];
            ldsm4(&b[0], buf + bBase + bSw);
            ldsm4(&b[4], buf + bBase + 2048 + bSw);
            #pragma unroll
            for (int mi = 0; mi < 4; mi++)
                ldsm4(a[mi], buf + aBase + mi * 2048 + aSw);
            #pragma unroll
            for (int mi = 0; mi < 4; mi++)
                #pragma unroll
                for (int ni = 0; ni < 4; ni++)
                    mma16816(d[mi][ni], a[mi], &b[ni*2]);
        }
    }

    // ---- register epilogue: y = hs@WC^T (3-term fp16), then gating ----
    uint32_t bh[4], bl[4];
    const uint32_t bO = sb + HT_OFF + 8192 +
        (uint32_t)((warp_n*16 + ((lane >> 4) << 3) + lh) * 32 + ((lane >> 3) & 1) * 16);
    ldsm4(bh, bO);
    ldsm4(bl, bO + 2048);
    const uint32_t aO = sb + HT_OFF +
        (uint32_t)((warp_m*64 + (lane & 15)) * 32 + (lane >> 4) * 16);

    const int ecol = j*64 + warp_n*16 + (lane & 3) * 2;
    const float2 bg0 = *(const float2*)(bg + ecol);
    const float2 bg1 = *(const float2*)(bg + ecol + 8);
    const float2 bd0 = *(const float2*)(bD + ecol);
    const float2 bd1 = *(const float2*)(bD + ecol + 8);

    #pragma unroll
    for (int mi = 0; mi < 4; mi++) {
        uint32_t ah[4], al[4];
        ldsm4(ah, aO + mi * 512);
        ldsm4(al, aO + 4096 + mi * 512);
        float ya[2][4] = {};
        #pragma unroll
        for (int nj = 0; nj < 2; nj++) {
            mma16816(ya[nj], ah, &bh[nj*2]);
            mma16816(ya[nj], ah, &bl[nj*2]);
            mma16816(ya[nj], al, &bh[nj*2]);
        }
        #pragma unroll
        for (int nj = 0; nj < 2; nj++) {
            float2 bgv = nj ? bg1 : bg0;
            float2 bdv = nj ? bd1 : bd0;
            #pragma unroll
            for (int hl = 0; hl < 2; hl++) {
                int row = m0 + warp_m*64 + mi*16 + (lane >> 2) + hl*8;
                float g0 = 1.0f / (1.0f + __expf(-(d[mi][2*nj][hl*2+0] + bgv.x)));
                float g1 = 1.0f / (1.0f + __expf(-(d[mi][2*nj][hl*2+1] + bgv.y)));
                float x0 = d[mi][2*nj+1][hl*2+0] + bdv.x;
                float x1 = d[mi][2*nj+1][hl*2+1] + bdv.y;
                float2 o;
                o.x = ya[nj][hl*2+0] * g0 + x0 * (1.0f - g0);
                o.y = ya[nj][hl*2+1] * g1 + x1 * (1.0f - g1);
                *(float2*)(out + (size_t)row * DD + ecol + nj*8) = o;
            }
        }
    }
}

// ---------------------------------------------------------------------------
extern "C" void kernel_launch(void* const* d_in, const int* in_sizes, int n_in,
                              void* d_out, int out_size)
{
    const float* x  = (const float*)d_in[0];
    const float* WA = (const float*)d_in[1];
    const float* WB = (const float*)d_in[2];
    const float* WC = (const float*)d_in[3];
    const float* WD = (const float*)d_in[4];
    const float* bD = (const float*)d_in[5];
    const float* Wg = (const float*)d_in[6];
    const float* bg = (const float*)d_in[7];
    float* out = (float*)d_out;

    cudaFuncSetAttribute(main_kernel,
                         cudaFuncAttributeMaxDynamicSharedMemorySize, SMEM_BYTES);
    cudaFuncSetAttribute(prep_kernel,
                         cudaFuncAttributeMaxDynamicSharedMemorySize, PREP_SMEM);

    wfuse_kernel<<<2240, 256>>>(Wg, WD, WA, WB, WC);
    prep_kernel<<<256, 256, PREP_SMEM>>>(x);
    scanf_kernel<<<16, 512>>>();
    main_kernel<<<dim3(16, 256), 256, SMEM_BYTES>>>(bD, bg, out);
}